// round 14
// baseline (speedup 1.0000x reference)
#include <cuda_runtime.h>
#include <cuda_bf16.h>
#include <math.h>
#include <stdint.h>

// ---------------------------------------------------------------------------
// GCN encoder on GB300: mma.sync bf16x3 GEMMs (fused pairs) + CSR gather agg.
// Interleaved hi/lo bf16 intermediates; packed {src,norm} edge records;
// stream-forked prep. R12 config; 3 CTAs/SM only on the low-pressure 64x64 GEMM.
// ---------------------------------------------------------------------------

#define NMAX 100000
#define NPAD 100224
#define EMAX 2000000

__device__ int   g_deg[NMAX];
__device__ int   g_rs[NMAX];
__device__ int   g_cursor[NMAX];
__device__ int   g_blk[512];
__device__ int2  g_cedge[EMAX];     // {src, norm bits}
__device__ uint32_t g_bufA[(size_t)NPAD * 128];
__device__ uint32_t g_bufB[(size_t)NPAD * 128];
__device__ uint32_t g_bufC[(size_t)NPAD * 128];
__device__ uint32_t g_wfrag[6 * 16384];

// ------------------------------ small helpers ------------------------------

__device__ __forceinline__ uint32_t smem_u32(const void* p) {
    uint32_t a;
    asm("{ .reg .u64 t; cvta.to.shared.u64 t, %1; cvt.u32.u64 %0, t; }" : "=r"(a) : "l"(p));
    return a;
}

__device__ __forceinline__ float il2f(uint32_t w) {
    __nv_bfloat162 p = *(__nv_bfloat162*)&w;
    return __bfloat162float(p.x) + __bfloat162float(p.y);
}

__device__ __forceinline__ uint32_t f2il(float v) {
    __nv_bfloat162 p;
    p.x = __float2bfloat16(v);
    p.y = __float2bfloat16(v - __bfloat162float(p.x));
    return *(uint32_t*)&p;
}

__device__ __forceinline__ void mma_bf16(float* c, const uint32_t* a, uint32_t b0, uint32_t b1) {
    asm volatile(
        "mma.sync.aligned.m16n8k16.row.col.f32.bf16.bf16.f32 "
        "{%0,%1,%2,%3}, {%4,%5,%6,%7}, {%8,%9}, {%0,%1,%2,%3};"
        : "+f"(c[0]), "+f"(c[1]), "+f"(c[2]), "+f"(c[3])
        : "r"(a[0]), "r"(a[1]), "r"(a[2]), "r"(a[3]), "r"(b0), "r"(b1));
}

__device__ __forceinline__ void ldsm_x4(uint32_t* r, uint32_t addr) {
    asm volatile("ldmatrix.sync.aligned.m8n8.x4.shared.b16 {%0,%1,%2,%3}, [%4];"
                 : "=r"(r[0]), "=r"(r[1]), "=r"(r[2]), "=r"(r[3]) : "r"(addr));
}

// ------------------------------ CSR build ----------------------------------

__global__ void deg_zero_kernel(int* __restrict__ deg, int n) {
    int i = blockIdx.x * 256 + threadIdx.x;
    if (i < n) deg[i] = 0;
}

__global__ void deg_count_kernel(const int* __restrict__ dst, int* __restrict__ deg, int E) {
    int e = blockIdx.x * 256 + threadIdx.x;
    if (e < E) atomicAdd(&deg[dst[e]], 1);
}

__global__ void scan1_kernel(const int* __restrict__ deg, int* __restrict__ tmp,
                             int* __restrict__ blk, int n) {
    __shared__ int sh[256];
    int tid = threadIdx.x;
    int i = blockIdx.x * 256 + tid;
    int v = (i < n) ? deg[i] : 0;
    sh[tid] = v;
    __syncthreads();
#pragma unroll
    for (int off = 1; off < 256; off <<= 1) {
        int t = (tid >= off) ? sh[tid - off] : 0;
        __syncthreads();
        sh[tid] += t;
        __syncthreads();
    }
    if (i < n) tmp[i] = sh[tid];
    if (tid == 255) blk[blockIdx.x] = sh[255];
}

__global__ void scan2_kernel(int* __restrict__ blk, int nb) {
    __shared__ int sh[512];
    int tid = threadIdx.x;
    int v = (tid < nb) ? blk[tid] : 0;
    sh[tid] = v;
    __syncthreads();
#pragma unroll
    for (int off = 1; off < 512; off <<= 1) {
        int t = (tid >= off) ? sh[tid - off] : 0;
        __syncthreads();
        sh[tid] += t;
        __syncthreads();
    }
    if (tid < nb) blk[tid] = sh[tid] - v;   // exclusive
}

__global__ void scan3_kernel(const int* __restrict__ tmp, const int* __restrict__ deg,
                             const int* __restrict__ blk, int* __restrict__ rs,
                             int* __restrict__ cursor, int n) {
    int i = blockIdx.x * 256 + threadIdx.x;
    if (i < n) {
        int v = tmp[i] - deg[i] + blk[blockIdx.x];
        rs[i] = v;
        cursor[i] = v;
    }
}

__global__ void scatter_kernel(const int* __restrict__ src, const int* __restrict__ dst,
                               const int* __restrict__ deg, int* __restrict__ cursor,
                               int2* __restrict__ cedge, int E) {
    int e = blockIdx.x * 256 + threadIdx.x;
    if (e >= E) return;
    int s = __ldg(&src[e]);
    int d = __ldg(&dst[e]);
    int pos = atomicAdd(&cursor[d], 1);
    float nrm = rsqrtf((float)(__ldg(&deg[s]) + 1)) * rsqrtf((float)(__ldg(&deg[d]) + 1));
    cedge[pos] = make_int2(s, __float_as_int(nrm));
}

// ---------------------- CSR gather aggregation (interleaved IO) -------------

template <int D, bool BIAS, bool RELU>
__global__ void csr_agg_kernel(const int* __restrict__ rs, const int* __restrict__ deg,
                               const int2* __restrict__ cedge,
                               const float* __restrict__ bias,
                               const uint32_t* __restrict__ h, uint32_t* __restrict__ out,
                               int n) {
    constexpr int LN = D / 4;
    int t = blockIdx.x * 256 + threadIdx.x;
    int d = t / LN;
    int lane = t % LN;
    if (d >= n) return;
    int start = __ldg(&rs[d]);
    int dg = __ldg(&deg[d]);
    float inv = 1.0f / (float)(dg + 1);
    size_t coff = (size_t)lane * 4;
    uint4 w = __ldg((const uint4*)(h + (size_t)d * D + coff));
    float4 acc;
    acc.x = il2f(w.x) * inv; acc.y = il2f(w.y) * inv;
    acc.z = il2f(w.z) * inv; acc.w = il2f(w.w) * inv;
    if (BIAS) {
        float4 b = *(const float4*)(bias + coff);
        acc.x += b.x; acc.y += b.y; acc.z += b.z; acc.w += b.w;
    }
    int j = start, end = start + dg;
    for (; j + 2 <= end; j += 2) {
        int2 e0 = __ldg(&cedge[j]);
        int2 e1 = __ldg(&cedge[j + 1]);
        float n0 = __int_as_float(e0.y), n1 = __int_as_float(e1.y);
        uint4 w0 = __ldg((const uint4*)(h + (size_t)e0.x * D + coff));
        uint4 w1 = __ldg((const uint4*)(h + (size_t)e1.x * D + coff));
        acc.x += il2f(w0.x) * n0 + il2f(w1.x) * n1;
        acc.y += il2f(w0.y) * n0 + il2f(w1.y) * n1;
        acc.z += il2f(w0.z) * n0 + il2f(w1.z) * n1;
        acc.w += il2f(w0.w) * n0 + il2f(w1.w) * n1;
    }
    if (j < end) {
        int2 e0 = __ldg(&cedge[j]);
        float n0 = __int_as_float(e0.y);
        uint4 w0 = __ldg((const uint4*)(h + (size_t)e0.x * D + coff));
        acc.x += il2f(w0.x) * n0; acc.y += il2f(w0.y) * n0;
        acc.z += il2f(w0.z) * n0; acc.w += il2f(w0.w) * n0;
    }
    if (RELU) {
        acc.x = fmaxf(acc.x, 0.f); acc.y = fmaxf(acc.y, 0.f);
        acc.z = fmaxf(acc.z, 0.f); acc.w = fmaxf(acc.w, 0.f);
    }
    uint4 o;
    o.x = f2il(acc.x); o.y = f2il(acc.y); o.z = f2il(acc.z); o.w = f2il(acc.w);
    *(uint4*)(out + (size_t)d * D + coff) = o;
}

// ------------------------- weight fragment packing --------------------------

__global__ void wprep_all_kernel(const float* __restrict__ w0, const float* __restrict__ w1,
                                 const float* __restrict__ w2, const float* __restrict__ w3,
                                 const float* __restrict__ w4, const float* __restrict__ w5,
                                 uint32_t* __restrict__ wf) {
    int idx = blockIdx.x * 256 + threadIdx.x;
    int tile = idx >> 5;
    if (tile >= 544) return;
    int lane = idx & 31;

    const float* W;
    int K, N, slot, base;
    bool TR;
    if (tile < 128)      { slot = 0; base = 0;   W = w0; K = 128; N = 128; TR = true;  }
    else if (tile < 256) { slot = 1; base = 128; W = w1; K = 128; N = 128; TR = false; }
    else if (tile < 320) { slot = 2; base = 256; W = w2; K = 128; N = 64;  TR = true;  }
    else if (tile < 352) { slot = 3; base = 320; W = w3; K = 64;  N = 64;  TR = false; }
    else if (tile < 416) { slot = 4; base = 352; W = w4; K = 64;  N = 128; TR = true;  }
    else                 { slot = 5; base = 416; W = w5; K = 128; N = 128; TR = false; }

    int t = tile - base;
    int NT = N / 8;
    int nt = t % NT;
    int kt = t / NT;
    int g = lane >> 2, tig = lane & 3;
    int nn = nt * 8 + g;
    uint32_t* out = wf + slot * 16384;
    int LOFF = K * N / 2;

#pragma unroll
    for (int r = 0; r < 2; r++) {
        int k0 = kt * 16 + tig * 2 + r * 8;
        float v0 = TR ? W[(size_t)k0 * N + nn] : W[(size_t)nn * K + k0];
        float v1 = TR ? W[(size_t)(k0 + 1) * N + nn] : W[(size_t)nn * K + k0 + 1];
        __nv_bfloat16 h0 = __float2bfloat16(v0), h1 = __float2bfloat16(v1);
        float l0 = v0 - __bfloat162float(h0), l1 = v1 - __bfloat162float(h1);
        __nv_bfloat162 hp; hp.x = h0; hp.y = h1;
        __nv_bfloat162 lp; lp.x = __float2bfloat16(l0); lp.y = __float2bfloat16(l1);
        out[(size_t)(t * 32 + lane) * 2 + r] = *(uint32_t*)&hp;
        out[LOFF + (size_t)(t * 32 + lane) * 2 + r] = *(uint32_t*)&lp;
    }
}

// ----------------------------- GEMM mainloop --------------------------------

template <int LDA, int KT, int NT, int MT>
__device__ __forceinline__ void gemm_mainloop(uint32_t a_base, uint32_t l_base,
                                              const uint32_t* __restrict__ WF,
                                              int wn, int lane, float (*acc)[8][4]) {
    constexpr int LOFF = KT * NT * 64;
#pragma unroll
    for (int kt = 0; kt < KT; kt++) {
        uint32_t ah[MT][4], al[MT][4];
#pragma unroll
        for (int mt = 0; mt < MT; mt++) {
            uint32_t off = (uint32_t)((mt * 16 * LDA + kt * 16) * 2);
            ldsm_x4(ah[mt], a_base + off);
            ldsm_x4(al[mt], l_base + off);
        }
#pragma unroll
        for (int nt = 0; nt < 8; nt++) {
            int gnt = wn * 8 + nt;
            const uint32_t* bp = WF + ((size_t)(kt * NT + gnt) * 32 + lane) * 2;
            uint2 bh = *(const uint2*)bp;
            uint2 bl = *(const uint2*)(bp + LOFF);
#pragma unroll
            for (int mt = 0; mt < MT; mt++) {
                mma_bf16(acc[mt][nt], ah[mt], bh.x, bh.y);
                mma_bf16(acc[mt][nt], ah[mt], bl.x, bl.y);
                mma_bf16(acc[mt][nt], al[mt], bh.x, bh.y);
            }
        }
    }
}

// ----------------------------- standard GEMM --------------------------------
// EPI: 0 = raw, 1 = relu(A + d) (K==N). Output interleaved.

template <int K, int N, bool F32IN, int EPI, int MINB>
__global__ __launch_bounds__(256, MINB) void mma_gemm_kernel(
    const float* __restrict__ A32, const uint32_t* __restrict__ Ail,
    const uint32_t* __restrict__ WF, uint32_t* __restrict__ Cil, int n) {
    constexpr int LDA = K + 8;
    constexpr int NT = N / 8;
    constexpr int KT = K / 16;
    constexpr int WN = N / 64;
    constexpr int WM = 8 / WN;
    constexpr int MT = 128 / (WM * 16);

    extern __shared__ __align__(16) char smem[];
    __nv_bfloat16* Ah = (__nv_bfloat16*)smem;
    __nv_bfloat16* Al = Ah + 128 * LDA;

    const int tid = threadIdx.x;
    const int w = tid >> 5;
    const int lane = tid & 31;
    const int g = lane >> 2, tig = lane & 3;
    const int row0 = blockIdx.x * 128;
    const int wm = w / WN;
    const int wn = w % WN;
    const uint32_t smem_base = smem_u32(smem);

    if (F32IN) {
        constexpr int KQ = K / 4;
        for (int idx = tid; idx < 128 * KQ; idx += 256) {
            int r = idx / KQ;
            int k0 = (idx - r * KQ) * 4;
            float4 v = make_float4(0.f, 0.f, 0.f, 0.f);
            if (row0 + r < n) v = *(const float4*)(A32 + (size_t)(row0 + r) * K + k0);
            uint32_t i0 = f2il(v.x), i1 = f2il(v.y), i2 = f2il(v.z), i3 = f2il(v.w);
            *(uint2*)(Ah + r * LDA + k0) =
                make_uint2(__byte_perm(i0, i1, 0x5410), __byte_perm(i2, i3, 0x5410));
            *(uint2*)(Al + r * LDA + k0) =
                make_uint2(__byte_perm(i0, i1, 0x7632), __byte_perm(i2, i3, 0x7632));
        }
    } else {
        constexpr int KW = K / 4;
        for (int idx = tid; idx < 128 * KW; idx += 256) {
            int r = idx / KW;
            int c4 = idx - r * KW;
            uint4 v = __ldg((const uint4*)(Ail + (size_t)(row0 + r) * K + c4 * 4));
            *(uint2*)(Ah + r * LDA + c4 * 4) =
                make_uint2(__byte_perm(v.x, v.y, 0x5410), __byte_perm(v.z, v.w, 0x5410));
            *(uint2*)(Al + r * LDA + c4 * 4) =
                make_uint2(__byte_perm(v.x, v.y, 0x7632), __byte_perm(v.z, v.w, 0x7632));
        }
    }
    __syncthreads();

    float acc[MT][8][4];
#pragma unroll
    for (int mt = 0; mt < MT; mt++)
#pragma unroll
        for (int nt = 0; nt < 8; nt++)
#pragma unroll
            for (int i = 0; i < 4; i++) acc[mt][nt][i] = 0.f;

    const uint32_t a_base =
        smem_base + (uint32_t)(((wm * MT * 16 + (lane & 15)) * LDA + (lane >> 4) * 8) * 2);
    const uint32_t l_base = a_base + (uint32_t)(128 * LDA * 2);
    gemm_mainloop<LDA, KT, NT, MT>(a_base, l_base, WF, wn, lane, acc);

#pragma unroll
    for (int mt = 0; mt < MT; mt++) {
        int rbase = wm * MT * 16 + mt * 16;
#pragma unroll
        for (int h = 0; h < 2; h++) {
            int rloc = rbase + g + h * 8;
            int row = row0 + rloc;
            if (row >= n) continue;
#pragma unroll
            for (int nt = 0; nt < 8; nt++) {
                int col = wn * 64 + nt * 8 + tig * 2;
                float v0 = acc[mt][nt][h * 2 + 0];
                float v1 = acc[mt][nt][h * 2 + 1];
                if (EPI == 1) {
                    __nv_bfloat162 rh = *(const __nv_bfloat162*)(Ah + rloc * LDA + col);
                    __nv_bfloat162 rl = *(const __nv_bfloat162*)(Al + rloc * LDA + col);
                    v0 = fmaxf(v0 + __bfloat162float(rh.x) + __bfloat162float(rl.x), 0.f);
                    v1 = fmaxf(v1 + __bfloat162float(rh.y) + __bfloat162float(rl.y), 0.f);
                }
                *(uint2*)(Cil + (size_t)row * N + col) = make_uint2(f2il(v0), f2il(v1));
            }
        }
    }
}

// ------------------------------ fused GEMM pair ------------------------------

template <int K1, int N1, int N2, bool BIAS1, bool OUTF32>
__global__ __launch_bounds__(256, 2) void fused_gemm_kernel(
    const uint32_t* __restrict__ Ail, const uint32_t* __restrict__ WF1,
    const uint32_t* __restrict__ WF2, float* __restrict__ C32,
    uint32_t* __restrict__ Cil, const float* __restrict__ bias1, int n) {
    constexpr int LDA1 = K1 + 8;
    constexpr int LDA2 = N1 + 8;
    constexpr bool INPLACE = !BIAS1;   // requires K1 == N1
    constexpr int KT1 = K1 / 16, NT1 = N1 / 8, WN1 = N1 / 64, WM1 = 8 / WN1,
                  MT1 = 128 / (WM1 * 16);
    constexpr int KT2 = N1 / 16, NT2 = N2 / 8, WN2 = N2 / 64, WM2 = 8 / WN2,
                  MT2 = 128 / (WM2 * 16);
    constexpr int MID_OFF = INPLACE ? 0 : 2 * 128 * LDA1;   // in bf16 elems

    extern __shared__ __align__(16) char smem[];
    __nv_bfloat16* Ah1 = (__nv_bfloat16*)smem;
    __nv_bfloat16* Al1 = Ah1 + 128 * LDA1;
    __nv_bfloat16* Ah2 = Ah1 + MID_OFF;
    __nv_bfloat16* Al2 = Ah2 + 128 * LDA2;

    const int tid = threadIdx.x;
    const int w = tid >> 5;
    const int lane = tid & 31;
    const int g = lane >> 2, tig = lane & 3;
    const int row0 = blockIdx.x * 128;
    const uint32_t smem_base = smem_u32(smem);

    {
        constexpr int KW = K1 / 4;
        for (int idx = tid; idx < 128 * KW; idx += 256) {
            int r = idx / KW;
            int c4 = idx - r * KW;
            uint4 v = __ldg((const uint4*)(Ail + (size_t)(row0 + r) * K1 + c4 * 4));
            *(uint2*)(Ah1 + r * LDA1 + c4 * 4) =
                make_uint2(__byte_perm(v.x, v.y, 0x5410), __byte_perm(v.z, v.w, 0x5410));
            *(uint2*)(Al1 + r * LDA1 + c4 * 4) =
                make_uint2(__byte_perm(v.x, v.y, 0x7632), __byte_perm(v.z, v.w, 0x7632));
        }
    }
    __syncthreads();

    // ---- GEMM 1 ----
    {
        const int wm = w / WN1;
        const int wn = w % WN1;
        float acc[MT1][8][4];
#pragma unroll
        for (int mt = 0; mt < MT1; mt++)
#pragma unroll
            for (int nt = 0; nt < 8; nt++)
#pragma unroll
                for (int i = 0; i < 4; i++) acc[mt][nt][i] = 0.f;

        const uint32_t a_base =
            smem_base + (uint32_t)(((wm * MT1 * 16 + (lane & 15)) * LDA1 + (lane >> 4) * 8) * 2);
        const uint32_t l_base = a_base + (uint32_t)(128 * LDA1 * 2);
        gemm_mainloop<LDA1, KT1, NT1, MT1>(a_base, l_base, WF1, wn, lane, acc);

        if (INPLACE) __syncthreads();

#pragma unroll
        for (int mt = 0; mt < MT1; mt++) {
            int rbase = wm * MT1 * 16 + mt * 16;
#pragma unroll
            for (int h = 0; h < 2; h++) {
                int rloc = rbase + g + h * 8;
#pragma unroll
                for (int nt = 0; nt < 8; nt++) {
                    int col = wn * 64 + nt * 8 + tig * 2;
                    float v0 = acc[mt][nt][h * 2 + 0];
                    float v1 = acc[mt][nt][h * 2 + 1];
                    if (BIAS1) {
                        v0 = fmaxf(v0 + __ldg(&bias1[col]), 0.f);
                        v1 = fmaxf(v1 + __ldg(&bias1[col + 1]), 0.f);
                    } else {
                        __nv_bfloat162 rh = *(const __nv_bfloat162*)(Ah1 + rloc * LDA1 + col);
                        __nv_bfloat162 rl = *(const __nv_bfloat162*)(Al1 + rloc * LDA1 + col);
                        v0 = fmaxf(v0 + __bfloat162float(rh.x) + __bfloat162float(rl.x), 0.f);
                        v1 = fmaxf(v1 + __bfloat162float(rh.y) + __bfloat162float(rl.y), 0.f);
                    }
                    __nv_bfloat16 h0 = __float2bfloat16(v0), h1 = __float2bfloat16(v1);
                    __nv_bfloat162 hp; hp.x = h0; hp.y = h1;
                    __nv_bfloat162 lp;
                    lp.x = __float2bfloat16(v0 - __bfloat162float(h0));
                    lp.y = __float2bfloat16(v1 - __bfloat162float(h1));
                    *(uint32_t*)(Ah2 + rloc * LDA2 + col) = *(uint32_t*)&hp;
                    *(uint32_t*)(Al2 + rloc * LDA2 + col) = *(uint32_t*)&lp;
                }
            }
        }
    }
    __syncthreads();

    // ---- GEMM 2 ----
    {
        const int wm = w / WN2;
        const int wn = w % WN2;
        float acc[MT2][8][4];
#pragma unroll
        for (int mt = 0; mt < MT2; mt++)
#pragma unroll
            for (int nt = 0; nt < 8; nt++)
#pragma unroll
                for (int i = 0; i < 4; i++) acc[mt][nt][i] = 0.f;

        const uint32_t a_base = smem_base + (uint32_t)(MID_OFF * 2) +
            (uint32_t)(((wm * MT2 * 16 + (lane & 15)) * LDA2 + (lane >> 4) * 8) * 2);
        const uint32_t l_base = a_base + (uint32_t)(128 * LDA2 * 2);
        gemm_mainloop<LDA2, KT2, NT2, MT2>(a_base, l_base, WF2, wn, lane, acc);

#pragma unroll
        for (int mt = 0; mt < MT2; mt++) {
            int rbase = wm * MT2 * 16 + mt * 16;
#pragma unroll
            for (int h = 0; h < 2; h++) {
                int rloc = rbase + g + h * 8;
                int row = row0 + rloc;
                if (row >= n) continue;
#pragma unroll
                for (int nt = 0; nt < 8; nt++) {
                    int col = wn * 64 + nt * 8 + tig * 2;
                    float v0 = acc[mt][nt][h * 2 + 0];
                    float v1 = acc[mt][nt][h * 2 + 1];
                    if (OUTF32) {
                        __nv_bfloat162 rh = *(const __nv_bfloat162*)(Ah2 + rloc * LDA2 + col);
                        __nv_bfloat162 rl = *(const __nv_bfloat162*)(Al2 + rloc * LDA2 + col);
                        v0 = fmaxf(v0 + __bfloat162float(rh.x) + __bfloat162float(rl.x), 0.f);
                        v1 = fmaxf(v1 + __bfloat162float(rh.y) + __bfloat162float(rl.y), 0.f);
                        float2 o; o.x = v0; o.y = v1;
                        *(float2*)(C32 + (size_t)row * N2 + col) = o;
                    } else {
                        *(uint2*)(Cil + (size_t)row * N2 + col) = make_uint2(f2il(v0), f2il(v1));
                    }
                }
            }
        }
    }
}

// --------------------------------- launchers --------------------------------

template <int K, int N, bool F32IN, int EPI, int MINB>
static void launch_std(const float* A32, const uint32_t* Ail, const uint32_t* WF,
                       uint32_t* Cil, int n) {
    constexpr int SMEM = 2 * 128 * (K + 8) * 2;
    auto kfn = mma_gemm_kernel<K, N, F32IN, EPI, MINB>;
    if (SMEM > 48 * 1024)
        cudaFuncSetAttribute(kfn, cudaFuncAttributeMaxDynamicSharedMemorySize, SMEM);
    kfn<<<(n + 127) / 128, 256, SMEM>>>(A32, Ail, WF, Cil, n);
}

template <int K1, int N1, int N2, bool BIAS1, bool OUTF32>
static void launch_fused(const uint32_t* Ail, const uint32_t* WF1, const uint32_t* WF2,
                         float* C32, uint32_t* Cil, const float* bias1, int n) {
    constexpr int SMEM = (BIAS1 ? (2 * 128 * (K1 + 8) + 2 * 128 * (N1 + 8))
                                : (2 * 128 * (K1 + 8))) * 2;
    auto kfn = fused_gemm_kernel<K1, N1, N2, BIAS1, OUTF32>;
    if (SMEM > 48 * 1024)
        cudaFuncSetAttribute(kfn, cudaFuncAttributeMaxDynamicSharedMemorySize, SMEM);
    kfn<<<(n + 127) / 128, 256, SMEM>>>(Ail, WF1, WF2, C32, Cil, bias1, n);
}

// --------------------------------- driver ----------------------------------

extern "C" void kernel_launch(void* const* d_in, const int* in_sizes, int n_in,
                              void* d_out, int out_size) {
    const float* x    = (const float*)d_in[0];
    const int*   ei   = (const int*)d_in[1];
    const float* g1w  = (const float*)d_in[2];
    const float* g1b  = (const float*)d_in[3];
    const float* fc2w = (const float*)d_in[4];
    const float* g3w  = (const float*)d_in[5];
    const float* g3b  = (const float*)d_in[6];
    const float* fc4w = (const float*)d_in[7];
    const float* g5w  = (const float*)d_in[8];
    const float* g5b  = (const float*)d_in[9];
    const float* fc6w = (const float*)d_in[10];

    int n = in_sizes[0] / 128;
    int E = in_sizes[1] / 2;
    const int* src = ei;
    const int* dst = ei + E;
    int nb = (n + 255) / 256;

    int *deg, *rs, *cursor, *blk;
    int2* cedge;
    uint32_t *bA, *bB, *bC, *wf;
    cudaGetSymbolAddress((void**)&deg, g_deg);
    cudaGetSymbolAddress((void**)&rs, g_rs);
    cudaGetSymbolAddress((void**)&cursor, g_cursor);
    cudaGetSymbolAddress((void**)&blk, g_blk);
    cudaGetSymbolAddress((void**)&cedge, g_cedge);
    cudaGetSymbolAddress((void**)&bA, g_bufA);
    cudaGetSymbolAddress((void**)&bB, g_bufB);
    cudaGetSymbolAddress((void**)&bC, g_bufC);
    cudaGetSymbolAddress((void**)&wf, g_wfrag);
    uint32_t* wf0 = wf;
    uint32_t* wf1 = wf + 16384;
    uint32_t* wf2 = wf + 2 * 16384;
    uint32_t* wf3 = wf + 3 * 16384;
    uint32_t* wf4 = wf + 4 * 16384;
    uint32_t* wf5 = wf + 5 * 16384;

    static cudaStream_t s_side = nullptr;
    static cudaEvent_t s_evF = nullptr, s_evJ = nullptr;
    if (!s_side) {
        cudaStreamCreateWithFlags(&s_side, cudaStreamNonBlocking);
        cudaEventCreateWithFlags(&s_evF, cudaEventDisableTiming);
        cudaEventCreateWithFlags(&s_evJ, cudaEventDisableTiming);
    }

    // ---- fork: CSR build on side stream, wprep+GEMM1 on main stream ----
    cudaEventRecord(s_evF, 0);
    cudaStreamWaitEvent(s_side, s_evF, 0);

    deg_zero_kernel<<<nb, 256, 0, s_side>>>(deg, n);
    deg_count_kernel<<<(E + 255) / 256, 256, 0, s_side>>>(dst, deg, E);
    scan1_kernel<<<nb, 256, 0, s_side>>>(deg, cursor, blk, n);
    scan2_kernel<<<1, 512, 0, s_side>>>(blk, nb);
    scan3_kernel<<<nb, 256, 0, s_side>>>(cursor, deg, blk, rs, cursor, n);
    scatter_kernel<<<(E + 255) / 256, 256, 0, s_side>>>(src, dst, deg, cursor, cedge, E);
    cudaEventRecord(s_evJ, s_side);

    wprep_all_kernel<<<68, 256>>>(g1w, fc2w, g3w, fc4w, g5w, fc6w, wf);
    launch_std<128, 128, true, 0, 2>(x, nullptr, wf0, bA, n);   // bA = x @ W1

    // ---- join ----
    cudaStreamWaitEvent(0, s_evJ, 0);

    // ---- layer 1 ----
    csr_agg_kernel<128, true, true><<<(n * 32 + 255) / 256, 256>>>(
        rs, deg, cedge, g1b, bA, bB, n);
    launch_fused<128, 128, 64, false, false>(bB, wf1, wf2, nullptr, bA, nullptr, n);

    // ---- layer 2 ----
    csr_agg_kernel<64, true, true><<<(n * 16 + 255) / 256, 256>>>(
        rs, deg, cedge, g3b, bA, bC, n);
    launch_std<64, 64, false, 1, 3>(nullptr, bC, wf3, bA, n);

    // ---- layer 3 (aggregate first at d=64) ----
    csr_agg_kernel<64, false, false><<<(n * 16 + 255) / 256, 256>>>(
        rs, deg, cedge, nullptr, bA, bB, n);
    launch_fused<64, 128, 128, true, true>(bB, wf4, wf5, (float*)d_out, nullptr, g5b, n);
}

// round 15
// speedup vs baseline: 1.4722x; 1.4722x over previous
#include <cuda_runtime.h>
#include <cuda_bf16.h>
#include <math.h>
#include <stdint.h>

// ---------------------------------------------------------------------------
// GCN encoder on GB300: mma.sync bf16x3 GEMMs (fused pairs) + CSR gather agg.
// Interleaved hi/lo bf16 intermediates; packed {src,norm} edge records;
// stream-forked prep (CSR build || wprep+GEMM1).  [R12 configuration]
// ---------------------------------------------------------------------------

#define NMAX 100000
#define NPAD 100224
#define EMAX 2000000

__device__ int   g_deg[NMAX];
__device__ int   g_rs[NMAX];
__device__ int   g_cursor[NMAX];
__device__ int   g_blk[512];
__device__ int2  g_cedge[EMAX];     // {src, norm bits}
__device__ uint32_t g_bufA[(size_t)NPAD * 128];
__device__ uint32_t g_bufB[(size_t)NPAD * 128];
__device__ uint32_t g_bufC[(size_t)NPAD * 128];
__device__ uint32_t g_wfrag[6 * 16384];

// ------------------------------ small helpers ------------------------------

__device__ __forceinline__ uint32_t smem_u32(const void* p) {
    uint32_t a;
    asm("{ .reg .u64 t; cvta.to.shared.u64 t, %1; cvt.u32.u64 %0, t; }" : "=r"(a) : "l"(p));
    return a;
}

__device__ __forceinline__ float il2f(uint32_t w) {
    __nv_bfloat162 p = *(__nv_bfloat162*)&w;
    return __bfloat162float(p.x) + __bfloat162float(p.y);
}

__device__ __forceinline__ uint32_t f2il(float v) {
    __nv_bfloat162 p;
    p.x = __float2bfloat16(v);
    p.y = __float2bfloat16(v - __bfloat162float(p.x));
    return *(uint32_t*)&p;
}

__device__ __forceinline__ void mma_bf16(float* c, const uint32_t* a, uint32_t b0, uint32_t b1) {
    asm volatile(
        "mma.sync.aligned.m16n8k16.row.col.f32.bf16.bf16.f32 "
        "{%0,%1,%2,%3}, {%4,%5,%6,%7}, {%8,%9}, {%0,%1,%2,%3};"
        : "+f"(c[0]), "+f"(c[1]), "+f"(c[2]), "+f"(c[3])
        : "r"(a[0]), "r"(a[1]), "r"(a[2]), "r"(a[3]), "r"(b0), "r"(b1));
}

__device__ __forceinline__ void ldsm_x4(uint32_t* r, uint32_t addr) {
    asm volatile("ldmatrix.sync.aligned.m8n8.x4.shared.b16 {%0,%1,%2,%3}, [%4];"
                 : "=r"(r[0]), "=r"(r[1]), "=r"(r[2]), "=r"(r[3]) : "r"(addr));
}

// ------------------------------ CSR build ----------------------------------

__global__ void deg_zero_kernel(int* __restrict__ deg, int n) {
    int i = blockIdx.x * 256 + threadIdx.x;
    if (i < n) deg[i] = 0;
}

__global__ void deg_count_kernel(const int* __restrict__ dst, int* __restrict__ deg, int E) {
    int e = blockIdx.x * 256 + threadIdx.x;
    if (e < E) atomicAdd(&deg[dst[e]], 1);
}

__global__ void scan1_kernel(const int* __restrict__ deg, int* __restrict__ tmp,
                             int* __restrict__ blk, int n) {
    __shared__ int sh[256];
    int tid = threadIdx.x;
    int i = blockIdx.x * 256 + tid;
    int v = (i < n) ? deg[i] : 0;
    sh[tid] = v;
    __syncthreads();
#pragma unroll
    for (int off = 1; off < 256; off <<= 1) {
        int t = (tid >= off) ? sh[tid - off] : 0;
        __syncthreads();
        sh[tid] += t;
        __syncthreads();
    }
    if (i < n) tmp[i] = sh[tid];
    if (tid == 255) blk[blockIdx.x] = sh[255];
}

__global__ void scan2_kernel(int* __restrict__ blk, int nb) {
    __shared__ int sh[512];
    int tid = threadIdx.x;
    int v = (tid < nb) ? blk[tid] : 0;
    sh[tid] = v;
    __syncthreads();
#pragma unroll
    for (int off = 1; off < 512; off <<= 1) {
        int t = (tid >= off) ? sh[tid - off] : 0;
        __syncthreads();
        sh[tid] += t;
        __syncthreads();
    }
    if (tid < nb) blk[tid] = sh[tid] - v;   // exclusive
}

__global__ void scan3_kernel(const int* __restrict__ tmp, const int* __restrict__ deg,
                             const int* __restrict__ blk, int* __restrict__ rs,
                             int* __restrict__ cursor, int n) {
    int i = blockIdx.x * 256 + threadIdx.x;
    if (i < n) {
        int v = tmp[i] - deg[i] + blk[blockIdx.x];
        rs[i] = v;
        cursor[i] = v;
    }
}

__global__ void scatter_kernel(const int* __restrict__ src, const int* __restrict__ dst,
                               const int* __restrict__ deg, int* __restrict__ cursor,
                               int2* __restrict__ cedge, int E) {
    int e = blockIdx.x * 256 + threadIdx.x;
    if (e >= E) return;
    int s = __ldg(&src[e]);
    int d = __ldg(&dst[e]);
    int pos = atomicAdd(&cursor[d], 1);
    float nrm = rsqrtf((float)(__ldg(&deg[s]) + 1)) * rsqrtf((float)(__ldg(&deg[d]) + 1));
    cedge[pos] = make_int2(s, __float_as_int(nrm));
}

// ---------------------- CSR gather aggregation (interleaved IO) -------------

template <int D, bool BIAS, bool RELU>
__global__ void csr_agg_kernel(const int* __restrict__ rs, const int* __restrict__ deg,
                               const int2* __restrict__ cedge,
                               const float* __restrict__ bias,
                               const uint32_t* __restrict__ h, uint32_t* __restrict__ out,
                               int n) {
    constexpr int LN = D / 4;
    int t = blockIdx.x * 256 + threadIdx.x;
    int d = t / LN;
    int lane = t % LN;
    if (d >= n) return;
    int start = __ldg(&rs[d]);
    int dg = __ldg(&deg[d]);
    float inv = 1.0f / (float)(dg + 1);
    size_t coff = (size_t)lane * 4;
    uint4 w = __ldg((const uint4*)(h + (size_t)d * D + coff));
    float4 acc;
    acc.x = il2f(w.x) * inv; acc.y = il2f(w.y) * inv;
    acc.z = il2f(w.z) * inv; acc.w = il2f(w.w) * inv;
    if (BIAS) {
        float4 b = *(const float4*)(bias + coff);
        acc.x += b.x; acc.y += b.y; acc.z += b.z; acc.w += b.w;
    }
    int j = start, end = start + dg;
    for (; j + 2 <= end; j += 2) {
        int2 e0 = __ldg(&cedge[j]);
        int2 e1 = __ldg(&cedge[j + 1]);
        float n0 = __int_as_float(e0.y), n1 = __int_as_float(e1.y);
        uint4 w0 = __ldg((const uint4*)(h + (size_t)e0.x * D + coff));
        uint4 w1 = __ldg((const uint4*)(h + (size_t)e1.x * D + coff));
        acc.x += il2f(w0.x) * n0 + il2f(w1.x) * n1;
        acc.y += il2f(w0.y) * n0 + il2f(w1.y) * n1;
        acc.z += il2f(w0.z) * n0 + il2f(w1.z) * n1;
        acc.w += il2f(w0.w) * n0 + il2f(w1.w) * n1;
    }
    if (j < end) {
        int2 e0 = __ldg(&cedge[j]);
        float n0 = __int_as_float(e0.y);
        uint4 w0 = __ldg((const uint4*)(h + (size_t)e0.x * D + coff));
        acc.x += il2f(w0.x) * n0; acc.y += il2f(w0.y) * n0;
        acc.z += il2f(w0.z) * n0; acc.w += il2f(w0.w) * n0;
    }
    if (RELU) {
        acc.x = fmaxf(acc.x, 0.f); acc.y = fmaxf(acc.y, 0.f);
        acc.z = fmaxf(acc.z, 0.f); acc.w = fmaxf(acc.w, 0.f);
    }
    uint4 o;
    o.x = f2il(acc.x); o.y = f2il(acc.y); o.z = f2il(acc.z); o.w = f2il(acc.w);
    *(uint4*)(out + (size_t)d * D + coff) = o;
}

// ------------------------- weight fragment packing --------------------------

__global__ void wprep_all_kernel(const float* __restrict__ w0, const float* __restrict__ w1,
                                 const float* __restrict__ w2, const float* __restrict__ w3,
                                 const float* __restrict__ w4, const float* __restrict__ w5,
                                 uint32_t* __restrict__ wf) {
    int idx = blockIdx.x * 256 + threadIdx.x;
    int tile = idx >> 5;
    if (tile >= 544) return;
    int lane = idx & 31;

    const float* W;
    int K, N, slot, base;
    bool TR;
    if (tile < 128)      { slot = 0; base = 0;   W = w0; K = 128; N = 128; TR = true;  }
    else if (tile < 256) { slot = 1; base = 128; W = w1; K = 128; N = 128; TR = false; }
    else if (tile < 320) { slot = 2; base = 256; W = w2; K = 128; N = 64;  TR = true;  }
    else if (tile < 352) { slot = 3; base = 320; W = w3; K = 64;  N = 64;  TR = false; }
    else if (tile < 416) { slot = 4; base = 352; W = w4; K = 64;  N = 128; TR = true;  }
    else                 { slot = 5; base = 416; W = w5; K = 128; N = 128; TR = false; }

    int t = tile - base;
    int NT = N / 8;
    int nt = t % NT;
    int kt = t / NT;
    int g = lane >> 2, tig = lane & 3;
    int nn = nt * 8 + g;
    uint32_t* out = wf + slot * 16384;
    int LOFF = K * N / 2;

#pragma unroll
    for (int r = 0; r < 2; r++) {
        int k0 = kt * 16 + tig * 2 + r * 8;
        float v0 = TR ? W[(size_t)k0 * N + nn] : W[(size_t)nn * K + k0];
        float v1 = TR ? W[(size_t)(k0 + 1) * N + nn] : W[(size_t)nn * K + k0 + 1];
        __nv_bfloat16 h0 = __float2bfloat16(v0), h1 = __float2bfloat16(v1);
        float l0 = v0 - __bfloat162float(h0), l1 = v1 - __bfloat162float(h1);
        __nv_bfloat162 hp; hp.x = h0; hp.y = h1;
        __nv_bfloat162 lp; lp.x = __float2bfloat16(l0); lp.y = __float2bfloat16(l1);
        out[(size_t)(t * 32 + lane) * 2 + r] = *(uint32_t*)&hp;
        out[LOFF + (size_t)(t * 32 + lane) * 2 + r] = *(uint32_t*)&lp;
    }
}

// ----------------------------- GEMM mainloop --------------------------------

template <int LDA, int KT, int NT, int MT>
__device__ __forceinline__ void gemm_mainloop(uint32_t a_base, uint32_t l_base,
                                              const uint32_t* __restrict__ WF,
                                              int wn, int lane, float (*acc)[8][4]) {
    constexpr int LOFF = KT * NT * 64;
#pragma unroll
    for (int kt = 0; kt < KT; kt++) {
        uint32_t ah[MT][4], al[MT][4];
#pragma unroll
        for (int mt = 0; mt < MT; mt++) {
            uint32_t off = (uint32_t)((mt * 16 * LDA + kt * 16) * 2);
            ldsm_x4(ah[mt], a_base + off);
            ldsm_x4(al[mt], l_base + off);
        }
#pragma unroll
        for (int nt = 0; nt < 8; nt++) {
            int gnt = wn * 8 + nt;
            const uint32_t* bp = WF + ((size_t)(kt * NT + gnt) * 32 + lane) * 2;
            uint2 bh = *(const uint2*)bp;
            uint2 bl = *(const uint2*)(bp + LOFF);
#pragma unroll
            for (int mt = 0; mt < MT; mt++) {
                mma_bf16(acc[mt][nt], ah[mt], bh.x, bh.y);
                mma_bf16(acc[mt][nt], ah[mt], bl.x, bl.y);
                mma_bf16(acc[mt][nt], al[mt], bh.x, bh.y);
            }
        }
    }
}

// ----------------------------- standard GEMM --------------------------------
// EPI: 0 = raw, 1 = relu(A + d) (K==N). Output interleaved.

template <int K, int N, bool F32IN, int EPI>
__global__ __launch_bounds__(256, 2) void mma_gemm_kernel(
    const float* __restrict__ A32, const uint32_t* __restrict__ Ail,
    const uint32_t* __restrict__ WF, uint32_t* __restrict__ Cil, int n) {
    constexpr int LDA = K + 8;
    constexpr int NT = N / 8;
    constexpr int KT = K / 16;
    constexpr int WN = N / 64;
    constexpr int WM = 8 / WN;
    constexpr int MT = 128 / (WM * 16);

    extern __shared__ __align__(16) char smem[];
    __nv_bfloat16* Ah = (__nv_bfloat16*)smem;
    __nv_bfloat16* Al = Ah + 128 * LDA;

    const int tid = threadIdx.x;
    const int w = tid >> 5;
    const int lane = tid & 31;
    const int g = lane >> 2, tig = lane & 3;
    const int row0 = blockIdx.x * 128;
    const int wm = w / WN;
    const int wn = w % WN;
    const uint32_t smem_base = smem_u32(smem);

    if (F32IN) {
        constexpr int KQ = K / 4;
        for (int idx = tid; idx < 128 * KQ; idx += 256) {
            int r = idx / KQ;
            int k0 = (idx - r * KQ) * 4;
            float4 v = make_float4(0.f, 0.f, 0.f, 0.f);
            if (row0 + r < n) v = *(const float4*)(A32 + (size_t)(row0 + r) * K + k0);
            uint32_t i0 = f2il(v.x), i1 = f2il(v.y), i2 = f2il(v.z), i3 = f2il(v.w);
            *(uint2*)(Ah + r * LDA + k0) =
                make_uint2(__byte_perm(i0, i1, 0x5410), __byte_perm(i2, i3, 0x5410));
            *(uint2*)(Al + r * LDA + k0) =
                make_uint2(__byte_perm(i0, i1, 0x7632), __byte_perm(i2, i3, 0x7632));
        }
    } else {
        constexpr int KW = K / 4;
        for (int idx = tid; idx < 128 * KW; idx += 256) {
            int r = idx / KW;
            int c4 = idx - r * KW;
            uint4 v = __ldg((const uint4*)(Ail + (size_t)(row0 + r) * K + c4 * 4));
            *(uint2*)(Ah + r * LDA + c4 * 4) =
                make_uint2(__byte_perm(v.x, v.y, 0x5410), __byte_perm(v.z, v.w, 0x5410));
            *(uint2*)(Al + r * LDA + c4 * 4) =
                make_uint2(__byte_perm(v.x, v.y, 0x7632), __byte_perm(v.z, v.w, 0x7632));
        }
    }
    __syncthreads();

    float acc[MT][8][4];
#pragma unroll
    for (int mt = 0; mt < MT; mt++)
#pragma unroll
        for (int nt = 0; nt < 8; nt++)
#pragma unroll
            for (int i = 0; i < 4; i++) acc[mt][nt][i] = 0.f;

    const uint32_t a_base =
        smem_base + (uint32_t)(((wm * MT * 16 + (lane & 15)) * LDA + (lane >> 4) * 8) * 2);
    const uint32_t l_base = a_base + (uint32_t)(128 * LDA * 2);
    gemm_mainloop<LDA, KT, NT, MT>(a_base, l_base, WF, wn, lane, acc);

#pragma unroll
    for (int mt = 0; mt < MT; mt++) {
        int rbase = wm * MT * 16 + mt * 16;
#pragma unroll
        for (int h = 0; h < 2; h++) {
            int rloc = rbase + g + h * 8;
            int row = row0 + rloc;
            if (row >= n) continue;
#pragma unroll
            for (int nt = 0; nt < 8; nt++) {
                int col = wn * 64 + nt * 8 + tig * 2;
                float v0 = acc[mt][nt][h * 2 + 0];
                float v1 = acc[mt][nt][h * 2 + 1];
                if (EPI == 1) {
                    __nv_bfloat162 rh = *(const __nv_bfloat162*)(Ah + rloc * LDA + col);
                    __nv_bfloat162 rl = *(const __nv_bfloat162*)(Al + rloc * LDA + col);
                    v0 = fmaxf(v0 + __bfloat162float(rh.x) + __bfloat162float(rl.x), 0.f);
                    v1 = fmaxf(v1 + __bfloat162float(rh.y) + __bfloat162float(rl.y), 0.f);
                }
                *(uint2*)(Cil + (size_t)row * N + col) = make_uint2(f2il(v0), f2il(v1));
            }
        }
    }
}

// ------------------------------ fused GEMM pair ------------------------------

template <int K1, int N1, int N2, bool BIAS1, bool OUTF32>
__global__ __launch_bounds__(256, 2) void fused_gemm_kernel(
    const uint32_t* __restrict__ Ail, const uint32_t* __restrict__ WF1,
    const uint32_t* __restrict__ WF2, float* __restrict__ C32,
    uint32_t* __restrict__ Cil, const float* __restrict__ bias1, int n) {
    constexpr int LDA1 = K1 + 8;
    constexpr int LDA2 = N1 + 8;
    constexpr bool INPLACE = !BIAS1;   // requires K1 == N1
    constexpr int KT1 = K1 / 16, NT1 = N1 / 8, WN1 = N1 / 64, WM1 = 8 / WN1,
                  MT1 = 128 / (WM1 * 16);
    constexpr int KT2 = N1 / 16, NT2 = N2 / 8, WN2 = N2 / 64, WM2 = 8 / WN2,
                  MT2 = 128 / (WM2 * 16);
    constexpr int MID_OFF = INPLACE ? 0 : 2 * 128 * LDA1;   // in bf16 elems

    extern __shared__ __align__(16) char smem[];
    __nv_bfloat16* Ah1 = (__nv_bfloat16*)smem;
    __nv_bfloat16* Al1 = Ah1 + 128 * LDA1;
    __nv_bfloat16* Ah2 = Ah1 + MID_OFF;
    __nv_bfloat16* Al2 = Ah2 + 128 * LDA2;

    const int tid = threadIdx.x;
    const int w = tid >> 5;
    const int lane = tid & 31;
    const int g = lane >> 2, tig = lane & 3;
    const int row0 = blockIdx.x * 128;
    const uint32_t smem_base = smem_u32(smem);

    {
        constexpr int KW = K1 / 4;
        for (int idx = tid; idx < 128 * KW; idx += 256) {
            int r = idx / KW;
            int c4 = idx - r * KW;
            uint4 v = __ldg((const uint4*)(Ail + (size_t)(row0 + r) * K1 + c4 * 4));
            *(uint2*)(Ah1 + r * LDA1 + c4 * 4) =
                make_uint2(__byte_perm(v.x, v.y, 0x5410), __byte_perm(v.z, v.w, 0x5410));
            *(uint2*)(Al1 + r * LDA1 + c4 * 4) =
                make_uint2(__byte_perm(v.x, v.y, 0x7632), __byte_perm(v.z, v.w, 0x7632));
        }
    }
    __syncthreads();

    // ---- GEMM 1 ----
    {
        const int wm = w / WN1;
        const int wn = w % WN1;
        float acc[MT1][8][4];
#pragma unroll
        for (int mt = 0; mt < MT1; mt++)
#pragma unroll
            for (int nt = 0; nt < 8; nt++)
#pragma unroll
                for (int i = 0; i < 4; i++) acc[mt][nt][i] = 0.f;

        const uint32_t a_base =
            smem_base + (uint32_t)(((wm * MT1 * 16 + (lane & 15)) * LDA1 + (lane >> 4) * 8) * 2);
        const uint32_t l_base = a_base + (uint32_t)(128 * LDA1 * 2);
        gemm_mainloop<LDA1, KT1, NT1, MT1>(a_base, l_base, WF1, wn, lane, acc);

        if (INPLACE) __syncthreads();

#pragma unroll
        for (int mt = 0; mt < MT1; mt++) {
            int rbase = wm * MT1 * 16 + mt * 16;
#pragma unroll
            for (int h = 0; h < 2; h++) {
                int rloc = rbase + g + h * 8;
#pragma unroll
                for (int nt = 0; nt < 8; nt++) {
                    int col = wn * 64 + nt * 8 + tig * 2;
                    float v0 = acc[mt][nt][h * 2 + 0];
                    float v1 = acc[mt][nt][h * 2 + 1];
                    if (BIAS1) {
                        v0 = fmaxf(v0 + __ldg(&bias1[col]), 0.f);
                        v1 = fmaxf(v1 + __ldg(&bias1[col + 1]), 0.f);
                    } else {
                        __nv_bfloat162 rh = *(const __nv_bfloat162*)(Ah1 + rloc * LDA1 + col);
                        __nv_bfloat162 rl = *(const __nv_bfloat162*)(Al1 + rloc * LDA1 + col);
                        v0 = fmaxf(v0 + __bfloat162float(rh.x) + __bfloat162float(rl.x), 0.f);
                        v1 = fmaxf(v1 + __bfloat162float(rh.y) + __bfloat162float(rl.y), 0.f);
                    }
                    __nv_bfloat16 h0 = __float2bfloat16(v0), h1 = __float2bfloat16(v1);
                    __nv_bfloat162 hp; hp.x = h0; hp.y = h1;
                    __nv_bfloat162 lp;
                    lp.x = __float2bfloat16(v0 - __bfloat162float(h0));
                    lp.y = __float2bfloat16(v1 - __bfloat162float(h1));
                    *(uint32_t*)(Ah2 + rloc * LDA2 + col) = *(uint32_t*)&hp;
                    *(uint32_t*)(Al2 + rloc * LDA2 + col) = *(uint32_t*)&lp;
                }
            }
        }
    }
    __syncthreads();

    // ---- GEMM 2 ----
    {
        const int wm = w / WN2;
        const int wn = w % WN2;
        float acc[MT2][8][4];
#pragma unroll
        for (int mt = 0; mt < MT2; mt++)
#pragma unroll
            for (int nt = 0; nt < 8; nt++)
#pragma unroll
                for (int i = 0; i < 4; i++) acc[mt][nt][i] = 0.f;

        const uint32_t a_base = smem_base + (uint32_t)(MID_OFF * 2) +
            (uint32_t)(((wm * MT2 * 16 + (lane & 15)) * LDA2 + (lane >> 4) * 8) * 2);
        const uint32_t l_base = a_base + (uint32_t)(128 * LDA2 * 2);
        gemm_mainloop<LDA2, KT2, NT2, MT2>(a_base, l_base, WF2, wn, lane, acc);

#pragma unroll
        for (int mt = 0; mt < MT2; mt++) {
            int rbase = wm * MT2 * 16 + mt * 16;
#pragma unroll
            for (int h = 0; h < 2; h++) {
                int rloc = rbase + g + h * 8;
                int row = row0 + rloc;
                if (row >= n) continue;
#pragma unroll
                for (int nt = 0; nt < 8; nt++) {
                    int col = wn * 64 + nt * 8 + tig * 2;
                    float v0 = acc[mt][nt][h * 2 + 0];
                    float v1 = acc[mt][nt][h * 2 + 1];
                    if (OUTF32) {
                        __nv_bfloat162 rh = *(const __nv_bfloat162*)(Ah2 + rloc * LDA2 + col);
                        __nv_bfloat162 rl = *(const __nv_bfloat162*)(Al2 + rloc * LDA2 + col);
                        v0 = fmaxf(v0 + __bfloat162float(rh.x) + __bfloat162float(rl.x), 0.f);
                        v1 = fmaxf(v1 + __bfloat162float(rh.y) + __bfloat162float(rl.y), 0.f);
                        float2 o; o.x = v0; o.y = v1;
                        *(float2*)(C32 + (size_t)row * N2 + col) = o;
                    } else {
                        *(uint2*)(Cil + (size_t)row * N2 + col) = make_uint2(f2il(v0), f2il(v1));
                    }
                }
            }
        }
    }
}

// --------------------------------- launchers --------------------------------

template <int K, int N, bool F32IN, int EPI>
static void launch_std(const float* A32, const uint32_t* Ail, const uint32_t* WF,
                       uint32_t* Cil, int n) {
    constexpr int SMEM = 2 * 128 * (K + 8) * 2;
    auto kfn = mma_gemm_kernel<K, N, F32IN, EPI>;
    if (SMEM > 48 * 1024)
        cudaFuncSetAttribute(kfn, cudaFuncAttributeMaxDynamicSharedMemorySize, SMEM);
    kfn<<<(n + 127) / 128, 256, SMEM>>>(A32, Ail, WF, Cil, n);
}

template <int K1, int N1, int N2, bool BIAS1, bool OUTF32>
static void launch_fused(const uint32_t* Ail, const uint32_t* WF1, const uint32_t* WF2,
                         float* C32, uint32_t* Cil, const float* bias1, int n) {
    constexpr int SMEM = (BIAS1 ? (2 * 128 * (K1 + 8) + 2 * 128 * (N1 + 8))
                                : (2 * 128 * (K1 + 8))) * 2;
    auto kfn = fused_gemm_kernel<K1, N1, N2, BIAS1, OUTF32>;
    if (SMEM > 48 * 1024)
        cudaFuncSetAttribute(kfn, cudaFuncAttributeMaxDynamicSharedMemorySize, SMEM);
    kfn<<<(n + 127) / 128, 256, SMEM>>>(Ail, WF1, WF2, C32, Cil, bias1, n);
}

// --------------------------------- driver ----------------------------------

extern "C" void kernel_launch(void* const* d_in, const int* in_sizes, int n_in,
                              void* d_out, int out_size) {
    const float* x    = (const float*)d_in[0];
    const int*   ei   = (const int*)d_in[1];
    const float* g1w  = (const float*)d_in[2];
    const float* g1b  = (const float*)d_in[3];
    const float* fc2w = (const float*)d_in[4];
    const float* g3w  = (const float*)d_in[5];
    const float* g3b  = (const float*)d_in[6];
    const float* fc4w = (const float*)d_in[7];
    const float* g5w  = (const float*)d_in[8];
    const float* g5b  = (const float*)d_in[9];
    const float* fc6w = (const float*)d_in[10];

    int n = in_sizes[0] / 128;
    int E = in_sizes[1] / 2;
    const int* src = ei;
    const int* dst = ei + E;
    int nb = (n + 255) / 256;

    int *deg, *rs, *cursor, *blk;
    int2* cedge;
    uint32_t *bA, *bB, *bC, *wf;
    cudaGetSymbolAddress((void**)&deg, g_deg);
    cudaGetSymbolAddress((void**)&rs, g_rs);
    cudaGetSymbolAddress((void**)&cursor, g_cursor);
    cudaGetSymbolAddress((void**)&blk, g_blk);
    cudaGetSymbolAddress((void**)&cedge, g_cedge);
    cudaGetSymbolAddress((void**)&bA, g_bufA);
    cudaGetSymbolAddress((void**)&bB, g_bufB);
    cudaGetSymbolAddress((void**)&bC, g_bufC);
    cudaGetSymbolAddress((void**)&wf, g_wfrag);
    uint32_t* wf0 = wf;
    uint32_t* wf1 = wf + 16384;
    uint32_t* wf2 = wf + 2 * 16384;
    uint32_t* wf3 = wf + 3 * 16384;
    uint32_t* wf4 = wf + 4 * 16384;
    uint32_t* wf5 = wf + 5 * 16384;

    static cudaStream_t s_side = nullptr;
    static cudaEvent_t s_evF = nullptr, s_evJ = nullptr;
    if (!s_side) {
        cudaStreamCreateWithFlags(&s_side, cudaStreamNonBlocking);
        cudaEventCreateWithFlags(&s_evF, cudaEventDisableTiming);
        cudaEventCreateWithFlags(&s_evJ, cudaEventDisableTiming);
    }

    // ---- fork: CSR build on side stream, wprep+GEMM1 on main stream ----
    cudaEventRecord(s_evF, 0);
    cudaStreamWaitEvent(s_side, s_evF, 0);

    deg_zero_kernel<<<nb, 256, 0, s_side>>>(deg, n);
    deg_count_kernel<<<(E + 255) / 256, 256, 0, s_side>>>(dst, deg, E);
    scan1_kernel<<<nb, 256, 0, s_side>>>(deg, cursor, blk, n);
    scan2_kernel<<<1, 512, 0, s_side>>>(blk, nb);
    scan3_kernel<<<nb, 256, 0, s_side>>>(cursor, deg, blk, rs, cursor, n);
    scatter_kernel<<<(E + 255) / 256, 256, 0, s_side>>>(src, dst, deg, cursor, cedge, E);
    cudaEventRecord(s_evJ, s_side);

    wprep_all_kernel<<<68, 256>>>(g1w, fc2w, g3w, fc4w, g5w, fc6w, wf);
    launch_std<128, 128, true, 0>(x, nullptr, wf0, bA, n);   // bA = x @ W1

    // ---- join ----
    cudaStreamWaitEvent(0, s_evJ, 0);

    // ---- layer 1 ----
    csr_agg_kernel<128, true, true><<<(n * 32 + 255) / 256, 256>>>(
        rs, deg, cedge, g1b, bA, bB, n);
    launch_fused<128, 128, 64, false, false>(bB, wf1, wf2, nullptr, bA, nullptr, n);

    // ---- layer 2 ----
    csr_agg_kernel<64, true, true><<<(n * 16 + 255) / 256, 256>>>(
        rs, deg, cedge, g3b, bA, bC, n);
    launch_std<64, 64, false, 1>(nullptr, bC, wf3, bA, n);

    // ---- layer 3 (aggregate first at d=64) ----
    csr_agg_kernel<64, false, false><<<(n * 16 + 255) / 256, 256>>>(
        rs, deg, cedge, nullptr, bA, bB, n);
    launch_fused<64, 128, 128, true, true>(bB, wf4, wf5, (float*)d_out, nullptr, g5b, n);
}

// round 16
// speedup vs baseline: 1.5102x; 1.0258x over previous
#include <cuda_runtime.h>
#include <cuda_bf16.h>
#include <math.h>
#include <stdint.h>

// ---------------------------------------------------------------------------
// GCN encoder on GB300: mma.sync bf16x3 GEMMs (64-row tiles, 4 CTAs/SM) +
// CSR gather agg. Interleaved hi/lo bf16 intermediates; packed {src,norm}
// edge records; stream-forked prep (CSR build || wprep+GEMM1).
// ---------------------------------------------------------------------------

#define NMAX 100000
#define NPAD 100224
#define EMAX 2000000

__device__ int   g_deg[NMAX];
__device__ int   g_rs[NMAX];
__device__ int   g_cursor[NMAX];
__device__ int   g_blk[512];
__device__ int2  g_cedge[EMAX];     // {src, norm bits}
__device__ uint32_t g_bufA[(size_t)NPAD * 128];
__device__ uint32_t g_bufB[(size_t)NPAD * 128];
__device__ uint32_t g_bufC[(size_t)NPAD * 128];
__device__ uint32_t g_wfrag[6 * 16384];

// ------------------------------ small helpers ------------------------------

__device__ __forceinline__ uint32_t smem_u32(const void* p) {
    uint32_t a;
    asm("{ .reg .u64 t; cvta.to.shared.u64 t, %1; cvt.u32.u64 %0, t; }" : "=r"(a) : "l"(p));
    return a;
}

__device__ __forceinline__ float il2f(uint32_t w) {
    __nv_bfloat162 p = *(__nv_bfloat162*)&w;
    return __bfloat162float(p.x) + __bfloat162float(p.y);
}

__device__ __forceinline__ uint32_t f2il(float v) {
    __nv_bfloat162 p;
    p.x = __float2bfloat16(v);
    p.y = __float2bfloat16(v - __bfloat162float(p.x));
    return *(uint32_t*)&p;
}

__device__ __forceinline__ void mma_bf16(float* c, const uint32_t* a, uint32_t b0, uint32_t b1) {
    asm volatile(
        "mma.sync.aligned.m16n8k16.row.col.f32.bf16.bf16.f32 "
        "{%0,%1,%2,%3}, {%4,%5,%6,%7}, {%8,%9}, {%0,%1,%2,%3};"
        : "+f"(c[0]), "+f"(c[1]), "+f"(c[2]), "+f"(c[3])
        : "r"(a[0]), "r"(a[1]), "r"(a[2]), "r"(a[3]), "r"(b0), "r"(b1));
}

__device__ __forceinline__ void ldsm_x4(uint32_t* r, uint32_t addr) {
    asm volatile("ldmatrix.sync.aligned.m8n8.x4.shared.b16 {%0,%1,%2,%3}, [%4];"
                 : "=r"(r[0]), "=r"(r[1]), "=r"(r[2]), "=r"(r[3]) : "r"(addr));
}

// ------------------------------ CSR build ----------------------------------

__global__ void deg_zero_kernel(int* __restrict__ deg, int n) {
    int i = blockIdx.x * 256 + threadIdx.x;
    if (i < n) deg[i] = 0;
}

__global__ void deg_count_kernel(const int* __restrict__ dst, int* __restrict__ deg, int E) {
    int e = blockIdx.x * 256 + threadIdx.x;
    if (e < E) atomicAdd(&deg[dst[e]], 1);
}

__global__ void scan1_kernel(const int* __restrict__ deg, int* __restrict__ tmp,
                             int* __restrict__ blk, int n) {
    __shared__ int sh[256];
    int tid = threadIdx.x;
    int i = blockIdx.x * 256 + tid;
    int v = (i < n) ? deg[i] : 0;
    sh[tid] = v;
    __syncthreads();
#pragma unroll
    for (int off = 1; off < 256; off <<= 1) {
        int t = (tid >= off) ? sh[tid - off] : 0;
        __syncthreads();
        sh[tid] += t;
        __syncthreads();
    }
    if (i < n) tmp[i] = sh[tid];
    if (tid == 255) blk[blockIdx.x] = sh[255];
}

__global__ void scan2_kernel(int* __restrict__ blk, int nb) {
    __shared__ int sh[512];
    int tid = threadIdx.x;
    int v = (tid < nb) ? blk[tid] : 0;
    sh[tid] = v;
    __syncthreads();
#pragma unroll
    for (int off = 1; off < 512; off <<= 1) {
        int t = (tid >= off) ? sh[tid - off] : 0;
        __syncthreads();
        sh[tid] += t;
        __syncthreads();
    }
    if (tid < nb) blk[tid] = sh[tid] - v;   // exclusive
}

__global__ void scan3_kernel(const int* __restrict__ tmp, const int* __restrict__ deg,
                             const int* __restrict__ blk, int* __restrict__ rs,
                             int* __restrict__ cursor, int n) {
    int i = blockIdx.x * 256 + threadIdx.x;
    if (i < n) {
        int v = tmp[i] - deg[i] + blk[blockIdx.x];
        rs[i] = v;
        cursor[i] = v;
    }
}

__global__ void scatter_kernel(const int* __restrict__ src, const int* __restrict__ dst,
                               const int* __restrict__ deg, int* __restrict__ cursor,
                               int2* __restrict__ cedge, int E) {
    int e = blockIdx.x * 256 + threadIdx.x;
    if (e >= E) return;
    int s = __ldg(&src[e]);
    int d = __ldg(&dst[e]);
    int pos = atomicAdd(&cursor[d], 1);
    float nrm = rsqrtf((float)(__ldg(&deg[s]) + 1)) * rsqrtf((float)(__ldg(&deg[d]) + 1));
    cedge[pos] = make_int2(s, __float_as_int(nrm));
}

// ---------------------- CSR gather aggregation (interleaved IO) -------------

template <int D, bool BIAS, bool RELU>
__global__ void csr_agg_kernel(const int* __restrict__ rs, const int* __restrict__ deg,
                               const int2* __restrict__ cedge,
                               const float* __restrict__ bias,
                               const uint32_t* __restrict__ h, uint32_t* __restrict__ out,
                               int n) {
    constexpr int LN = D / 4;
    int t = blockIdx.x * 256 + threadIdx.x;
    int d = t / LN;
    int lane = t % LN;
    if (d >= n) return;
    int start = __ldg(&rs[d]);
    int dg = __ldg(&deg[d]);
    float inv = 1.0f / (float)(dg + 1);
    size_t coff = (size_t)lane * 4;
    uint4 w = __ldg((const uint4*)(h + (size_t)d * D + coff));
    float4 acc;
    acc.x = il2f(w.x) * inv; acc.y = il2f(w.y) * inv;
    acc.z = il2f(w.z) * inv; acc.w = il2f(w.w) * inv;
    if (BIAS) {
        float4 b = *(const float4*)(bias + coff);
        acc.x += b.x; acc.y += b.y; acc.z += b.z; acc.w += b.w;
    }
    int j = start, end = start + dg;
    for (; j + 2 <= end; j += 2) {
        int2 e0 = __ldg(&cedge[j]);
        int2 e1 = __ldg(&cedge[j + 1]);
        float n0 = __int_as_float(e0.y), n1 = __int_as_float(e1.y);
        uint4 w0 = __ldg((const uint4*)(h + (size_t)e0.x * D + coff));
        uint4 w1 = __ldg((const uint4*)(h + (size_t)e1.x * D + coff));
        acc.x += il2f(w0.x) * n0 + il2f(w1.x) * n1;
        acc.y += il2f(w0.y) * n0 + il2f(w1.y) * n1;
        acc.z += il2f(w0.z) * n0 + il2f(w1.z) * n1;
        acc.w += il2f(w0.w) * n0 + il2f(w1.w) * n1;
    }
    if (j < end) {
        int2 e0 = __ldg(&cedge[j]);
        float n0 = __int_as_float(e0.y);
        uint4 w0 = __ldg((const uint4*)(h + (size_t)e0.x * D + coff));
        acc.x += il2f(w0.x) * n0; acc.y += il2f(w0.y) * n0;
        acc.z += il2f(w0.z) * n0; acc.w += il2f(w0.w) * n0;
    }
    if (RELU) {
        acc.x = fmaxf(acc.x, 0.f); acc.y = fmaxf(acc.y, 0.f);
        acc.z = fmaxf(acc.z, 0.f); acc.w = fmaxf(acc.w, 0.f);
    }
    uint4 o;
    o.x = f2il(acc.x); o.y = f2il(acc.y); o.z = f2il(acc.z); o.w = f2il(acc.w);
    *(uint4*)(out + (size_t)d * D + coff) = o;
}

// ------------------------- weight fragment packing --------------------------

__global__ void wprep_all_kernel(const float* __restrict__ w0, const float* __restrict__ w1,
                                 const float* __restrict__ w2, const float* __restrict__ w3,
                                 const float* __restrict__ w4, const float* __restrict__ w5,
                                 uint32_t* __restrict__ wf) {
    int idx = blockIdx.x * 256 + threadIdx.x;
    int tile = idx >> 5;
    if (tile >= 544) return;
    int lane = idx & 31;

    const float* W;
    int K, N, slot, base;
    bool TR;
    if (tile < 128)      { slot = 0; base = 0;   W = w0; K = 128; N = 128; TR = true;  }
    else if (tile < 256) { slot = 1; base = 128; W = w1; K = 128; N = 128; TR = false; }
    else if (tile < 320) { slot = 2; base = 256; W = w2; K = 128; N = 64;  TR = true;  }
    else if (tile < 352) { slot = 3; base = 320; W = w3; K = 64;  N = 64;  TR = false; }
    else if (tile < 416) { slot = 4; base = 352; W = w4; K = 64;  N = 128; TR = true;  }
    else                 { slot = 5; base = 416; W = w5; K = 128; N = 128; TR = false; }

    int t = tile - base;
    int NT = N / 8;
    int nt = t % NT;
    int kt = t / NT;
    int g = lane >> 2, tig = lane & 3;
    int nn = nt * 8 + g;
    uint32_t* out = wf + slot * 16384;
    int LOFF = K * N / 2;

#pragma unroll
    for (int r = 0; r < 2; r++) {
        int k0 = kt * 16 + tig * 2 + r * 8;
        float v0 = TR ? W[(size_t)k0 * N + nn] : W[(size_t)nn * K + k0];
        float v1 = TR ? W[(size_t)(k0 + 1) * N + nn] : W[(size_t)nn * K + k0 + 1];
        __nv_bfloat16 h0 = __float2bfloat16(v0), h1 = __float2bfloat16(v1);
        float l0 = v0 - __bfloat162float(h0), l1 = v1 - __bfloat162float(h1);
        __nv_bfloat162 hp; hp.x = h0; hp.y = h1;
        __nv_bfloat162 lp; lp.x = __float2bfloat16(l0); lp.y = __float2bfloat16(l1);
        out[(size_t)(t * 32 + lane) * 2 + r] = *(uint32_t*)&hp;
        out[LOFF + (size_t)(t * 32 + lane) * 2 + r] = *(uint32_t*)&lp;
    }
}

// ----------------------------- GEMM mainloop --------------------------------
// 64-row tile: 8 warps = 4(M) x 2(N); each warp one m16 tile, NW n8-tiles.

template <int LDA, int KT, int NT, int NW>
__device__ __forceinline__ void gemm_mainloop(uint32_t a_base, uint32_t l_base,
                                              const uint32_t* __restrict__ WF,
                                              int wn, int lane, float (*acc)[4]) {
    constexpr int LOFF = KT * NT * 64;
#pragma unroll
    for (int kt = 0; kt < KT; kt++) {
        uint32_t ah[4], al[4];
        uint32_t off = (uint32_t)((kt * 16) * 2);
        ldsm_x4(ah, a_base + off);
        ldsm_x4(al, l_base + off);
#pragma unroll
        for (int nt = 0; nt < NW; nt++) {
            int gnt = wn * NW + nt;
            const uint32_t* bp = WF + ((size_t)(kt * NT + gnt) * 32 + lane) * 2;
            uint2 bh = *(const uint2*)bp;
            uint2 bl = *(const uint2*)(bp + LOFF);
            mma_bf16(acc[nt], ah, bh.x, bh.y);
            mma_bf16(acc[nt], ah, bl.x, bl.y);
            mma_bf16(acc[nt], al, bh.x, bh.y);
        }
    }
}

// ----------------------------- standard GEMM --------------------------------
// EPI: 0 = raw, 1 = relu(A + d) (K==N). Output interleaved.

template <int K, int N, bool F32IN, int EPI>
__global__ void mma_gemm_kernel(
    const float* __restrict__ A32, const uint32_t* __restrict__ Ail,
    const uint32_t* __restrict__ WF, uint32_t* __restrict__ Cil, int n) {
    constexpr int LDA = K + 8;
    constexpr int NT = N / 8;
    constexpr int KT = K / 16;
    constexpr int NW = N / 16;      // n8-tiles per warp (WN=2)

    extern __shared__ __align__(16) char smem[];
    __nv_bfloat16* Ah = (__nv_bfloat16*)smem;
    __nv_bfloat16* Al = Ah + 64 * LDA;

    const int tid = threadIdx.x;
    const int w = tid >> 5;
    const int lane = tid & 31;
    const int g = lane >> 2, tig = lane & 3;
    const int row0 = blockIdx.x * 64;
    const int wm = w >> 1;          // 0..3
    const int wn = w & 1;           // 0..1
    const uint32_t smem_base = smem_u32(smem);

    if (F32IN) {
        constexpr int KQ = K / 4;
        for (int idx = tid; idx < 64 * KQ; idx += 256) {
            int r = idx / KQ;
            int k0 = (idx - r * KQ) * 4;
            float4 v = make_float4(0.f, 0.f, 0.f, 0.f);
            if (row0 + r < n) v = *(const float4*)(A32 + (size_t)(row0 + r) * K + k0);
            uint32_t i0 = f2il(v.x), i1 = f2il(v.y), i2 = f2il(v.z), i3 = f2il(v.w);
            *(uint2*)(Ah + r * LDA + k0) =
                make_uint2(__byte_perm(i0, i1, 0x5410), __byte_perm(i2, i3, 0x5410));
            *(uint2*)(Al + r * LDA + k0) =
                make_uint2(__byte_perm(i0, i1, 0x7632), __byte_perm(i2, i3, 0x7632));
        }
    } else {
        constexpr int KW = K / 4;
        for (int idx = tid; idx < 64 * KW; idx += 256) {
            int r = idx / KW;
            int c4 = idx - r * KW;
            uint4 v = __ldg((const uint4*)(Ail + (size_t)(row0 + r) * K + c4 * 4));
            *(uint2*)(Ah + r * LDA + c4 * 4) =
                make_uint2(__byte_perm(v.x, v.y, 0x5410), __byte_perm(v.z, v.w, 0x5410));
            *(uint2*)(Al + r * LDA + c4 * 4) =
                make_uint2(__byte_perm(v.x, v.y, 0x7632), __byte_perm(v.z, v.w, 0x7632));
        }
    }
    __syncthreads();

    float acc[NW][4];
#pragma unroll
    for (int nt = 0; nt < NW; nt++)
#pragma unroll
        for (int i = 0; i < 4; i++) acc[nt][i] = 0.f;

    const uint32_t a_base =
        smem_base + (uint32_t)(((wm * 16 + (lane & 15)) * LDA + (lane >> 4) * 8) * 2);
    const uint32_t l_base = a_base + (uint32_t)(64 * LDA * 2);
    gemm_mainloop<LDA, KT, NT, NW>(a_base, l_base, WF, wn, lane, acc);

#pragma unroll
    for (int h = 0; h < 2; h++) {
        int rloc = wm * 16 + g + h * 8;
        int row = row0 + rloc;
        if (row >= n) continue;
#pragma unroll
        for (int nt = 0; nt < NW; nt++) {
            int col = (wn * NW + nt) * 8 + tig * 2;
            float v0 = acc[nt][h * 2 + 0];
            float v1 = acc[nt][h * 2 + 1];
            if (EPI == 1) {
                __nv_bfloat162 rh = *(const __nv_bfloat162*)(Ah + rloc * LDA + col);
                __nv_bfloat162 rl = *(const __nv_bfloat162*)(Al + rloc * LDA + col);
                v0 = fmaxf(v0 + __bfloat162float(rh.x) + __bfloat162float(rl.x), 0.f);
                v1 = fmaxf(v1 + __bfloat162float(rh.y) + __bfloat162float(rl.y), 0.f);
            }
            *(uint2*)(Cil + (size_t)row * N + col) = make_uint2(f2il(v0), f2il(v1));
        }
    }
}

// ------------------------------ fused GEMM pair ------------------------------

template <int K1, int N1, int N2, bool BIAS1, bool OUTF32>
__global__ void fused_gemm_kernel(
    const uint32_t* __restrict__ Ail, const uint32_t* __restrict__ WF1,
    const uint32_t* __restrict__ WF2, float* __restrict__ C32,
    uint32_t* __restrict__ Cil, const float* __restrict__ bias1, int n) {
    constexpr int LDA1 = K1 + 8;
    constexpr int LDA2 = N1 + 8;
    constexpr bool INPLACE = !BIAS1;   // requires K1 == N1
    constexpr int KT1 = K1 / 16, NT1 = N1 / 8, NW1 = N1 / 16;
    constexpr int KT2 = N1 / 16, NT2 = N2 / 8, NW2 = N2 / 16;
    constexpr int MID_OFF = INPLACE ? 0 : 2 * 64 * LDA1;   // in bf16 elems

    extern __shared__ __align__(16) char smem[];
    __nv_bfloat16* Ah1 = (__nv_bfloat16*)smem;
    __nv_bfloat16* Al1 = Ah1 + 64 * LDA1;
    __nv_bfloat16* Ah2 = Ah1 + MID_OFF;
    __nv_bfloat16* Al2 = Ah2 + 64 * LDA2;

    const int tid = threadIdx.x;
    const int w = tid >> 5;
    const int lane = tid & 31;
    const int g = lane >> 2, tig = lane & 3;
    const int row0 = blockIdx.x * 64;
    const int wm = w >> 1;
    const int wn = w & 1;
    const uint32_t smem_base = smem_u32(smem);

    {
        constexpr int KW = K1 / 4;
        for (int idx = tid; idx < 64 * KW; idx += 256) {
            int r = idx / KW;
            int c4 = idx - r * KW;
            uint4 v = __ldg((const uint4*)(Ail + (size_t)(row0 + r) * K1 + c4 * 4));
            *(uint2*)(Ah1 + r * LDA1 + c4 * 4) =
                make_uint2(__byte_perm(v.x, v.y, 0x5410), __byte_perm(v.z, v.w, 0x5410));
            *(uint2*)(Al1 + r * LDA1 + c4 * 4) =
                make_uint2(__byte_perm(v.x, v.y, 0x7632), __byte_perm(v.z, v.w, 0x7632));
        }
    }
    __syncthreads();

    // ---- GEMM 1 ----
    {
        float acc[NW1][4];
#pragma unroll
        for (int nt = 0; nt < NW1; nt++)
#pragma unroll
            for (int i = 0; i < 4; i++) acc[nt][i] = 0.f;

        const uint32_t a_base =
            smem_base + (uint32_t)(((wm * 16 + (lane & 15)) * LDA1 + (lane >> 4) * 8) * 2);
        const uint32_t l_base = a_base + (uint32_t)(64 * LDA1 * 2);
        gemm_mainloop<LDA1, KT1, NT1, NW1>(a_base, l_base, WF1, wn, lane, acc);

        if (INPLACE) __syncthreads();

#pragma unroll
        for (int h = 0; h < 2; h++) {
            int rloc = wm * 16 + g + h * 8;
#pragma unroll
            for (int nt = 0; nt < NW1; nt++) {
                int col = (wn * NW1 + nt) * 8 + tig * 2;
                float v0 = acc[nt][h * 2 + 0];
                float v1 = acc[nt][h * 2 + 1];
                if (BIAS1) {
                    v0 = fmaxf(v0 + __ldg(&bias1[col]), 0.f);
                    v1 = fmaxf(v1 + __ldg(&bias1[col + 1]), 0.f);
                } else {
                    __nv_bfloat162 rh = *(const __nv_bfloat162*)(Ah1 + rloc * LDA1 + col);
                    __nv_bfloat162 rl = *(const __nv_bfloat162*)(Al1 + rloc * LDA1 + col);
                    v0 = fmaxf(v0 + __bfloat162float(rh.x) + __bfloat162float(rl.x), 0.f);
                    v1 = fmaxf(v1 + __bfloat162float(rh.y) + __bfloat162float(rl.y), 0.f);
                }
                __nv_bfloat16 h0 = __float2bfloat16(v0), h1 = __float2bfloat16(v1);
                __nv_bfloat162 hp; hp.x = h0; hp.y = h1;
                __nv_bfloat162 lp;
                lp.x = __float2bfloat16(v0 - __bfloat162float(h0));
                lp.y = __float2bfloat16(v1 - __bfloat162float(h1));
                *(uint32_t*)(Ah2 + rloc * LDA2 + col) = *(uint32_t*)&hp;
                *(uint32_t*)(Al2 + rloc * LDA2 + col) = *(uint32_t*)&lp;
            }
        }
    }
    __syncthreads();

    // ---- GEMM 2 ----
    {
        float acc[NW2][4];
#pragma unroll
        for (int nt = 0; nt < NW2; nt++)
#pragma unroll
            for (int i = 0; i < 4; i++) acc[nt][i] = 0.f;

        const uint32_t a_base = smem_base + (uint32_t)(MID_OFF * 2) +
            (uint32_t)(((wm * 16 + (lane & 15)) * LDA2 + (lane >> 4) * 8) * 2);
        const uint32_t l_base = a_base + (uint32_t)(64 * LDA2 * 2);
        gemm_mainloop<LDA2, KT2, NT2, NW2>(a_base, l_base, WF2, wn, lane, acc);

#pragma unroll
        for (int h = 0; h < 2; h++) {
            int rloc = wm * 16 + g + h * 8;
            int row = row0 + rloc;
            if (row >= n) continue;
#pragma unroll
            for (int nt = 0; nt < NW2; nt++) {
                int col = (wn * NW2 + nt) * 8 + tig * 2;
                float v0 = acc[nt][h * 2 + 0];
                float v1 = acc[nt][h * 2 + 1];
                if (OUTF32) {
                    __nv_bfloat162 rh = *(const __nv_bfloat162*)(Ah2 + rloc * LDA2 + col);
                    __nv_bfloat162 rl = *(const __nv_bfloat162*)(Al2 + rloc * LDA2 + col);
                    v0 = fmaxf(v0 + __bfloat162float(rh.x) + __bfloat162float(rl.x), 0.f);
                    v1 = fmaxf(v1 + __bfloat162float(rh.y) + __bfloat162float(rl.y), 0.f);
                    float2 o; o.x = v0; o.y = v1;
                    *(float2*)(C32 + (size_t)row * N2 + col) = o;
                } else {
                    *(uint2*)(Cil + (size_t)row * N2 + col) = make_uint2(f2il(v0), f2il(v1));
                }
            }
        }
    }
}

// --------------------------------- launchers --------------------------------

template <int K, int N, bool F32IN, int EPI>
static void launch_std(const float* A32, const uint32_t* Ail, const uint32_t* WF,
                       uint32_t* Cil, int n) {
    constexpr int SMEM = 2 * 64 * (K + 8) * 2;
    auto kfn = mma_gemm_kernel<K, N, F32IN, EPI>;
    if (SMEM > 48 * 1024)
        cudaFuncSetAttribute(kfn, cudaFuncAttributeMaxDynamicSharedMemorySize, SMEM);
    kfn<<<(n + 63) / 64, 256, SMEM>>>(A32, Ail, WF, Cil, n);
}

template <int K1, int N1, int N2, bool BIAS1, bool OUTF32>
static void launch_fused(const uint32_t* Ail, const uint32_t* WF1, const uint32_t* WF2,
                         float* C32, uint32_t* Cil, const float* bias1, int n) {
    constexpr int SMEM = (BIAS1 ? (2 * 64 * (K1 + 8) + 2 * 64 * (N1 + 8))
                                : (2 * 64 * (K1 + 8))) * 2;
    auto kfn = fused_gemm_kernel<K1, N1, N2, BIAS1, OUTF32>;
    if (SMEM > 48 * 1024)
        cudaFuncSetAttribute(kfn, cudaFuncAttributeMaxDynamicSharedMemorySize, SMEM);
    kfn<<<(n + 63) / 64, 256, SMEM>>>(Ail, WF1, WF2, C32, Cil, bias1, n);
}

// --------------------------------- driver ----------------------------------

extern "C" void kernel_launch(void* const* d_in, const int* in_sizes, int n_in,
                              void* d_out, int out_size) {
    const float* x    = (const float*)d_in[0];
    const int*   ei   = (const int*)d_in[1];
    const float* g1w  = (const float*)d_in[2];
    const float* g1b  = (const float*)d_in[3];
    const float* fc2w = (const float*)d_in[4];
    const float* g3w  = (const float*)d_in[5];
    const float* g3b  = (const float*)d_in[6];
    const float* fc4w = (const float*)d_in[7];
    const float* g5w  = (const float*)d_in[8];
    const float* g5b  = (const float*)d_in[9];
    const float* fc6w = (const float*)d_in[10];

    int n = in_sizes[0] / 128;
    int E = in_sizes[1] / 2;
    const int* src = ei;
    const int* dst = ei + E;
    int nb = (n + 255) / 256;

    int *deg, *rs, *cursor, *blk;
    int2* cedge;
    uint32_t *bA, *bB, *bC, *wf;
    cudaGetSymbolAddress((void**)&deg, g_deg);
    cudaGetSymbolAddress((void**)&rs, g_rs);
    cudaGetSymbolAddress((void**)&cursor, g_cursor);
    cudaGetSymbolAddress((void**)&blk, g_blk);
    cudaGetSymbolAddress((void**)&cedge, g_cedge);
    cudaGetSymbolAddress((void**)&bA, g_bufA);
    cudaGetSymbolAddress((void**)&bB, g_bufB);
    cudaGetSymbolAddress((void**)&bC, g_bufC);
    cudaGetSymbolAddress((void**)&wf, g_wfrag);
    uint32_t* wf0 = wf;
    uint32_t* wf1 = wf + 16384;
    uint32_t* wf2 = wf + 2 * 16384;
    uint32_t* wf3 = wf + 3 * 16384;
    uint32_t* wf4 = wf + 4 * 16384;
    uint32_t* wf5 = wf + 5 * 16384;

    static cudaStream_t s_side = nullptr;
    static cudaEvent_t s_evF = nullptr, s_evJ = nullptr;
    if (!s_side) {
        cudaStreamCreateWithFlags(&s_side, cudaStreamNonBlocking);
        cudaEventCreateWithFlags(&s_evF, cudaEventDisableTiming);
        cudaEventCreateWithFlags(&s_evJ, cudaEventDisableTiming);
    }

    // ---- fork: CSR build on side stream, wprep+GEMM1 on main stream ----
    cudaEventRecord(s_evF, 0);
    cudaStreamWaitEvent(s_side, s_evF, 0);

    deg_zero_kernel<<<nb, 256, 0, s_side>>>(deg, n);
    deg_count_kernel<<<(E + 255) / 256, 256, 0, s_side>>>(dst, deg, E);
    scan1_kernel<<<nb, 256, 0, s_side>>>(deg, cursor, blk, n);
    scan2_kernel<<<1, 512, 0, s_side>>>(blk, nb);
    scan3_kernel<<<nb, 256, 0, s_side>>>(cursor, deg, blk, rs, cursor, n);
    scatter_kernel<<<(E + 255) / 256, 256, 0, s_side>>>(src, dst, deg, cursor, cedge, E);
    cudaEventRecord(s_evJ, s_side);

    wprep_all_kernel<<<68, 256>>>(g1w, fc2w, g3w, fc4w, g5w, fc6w, wf);
    launch_std<128, 128, true, 0>(x, nullptr, wf0, bA, n);   // bA = x @ W1

    // ---- join ----
    cudaStreamWaitEvent(0, s_evJ, 0);

    // ---- layer 1 ----
    csr_agg_kernel<128, true, true><<<(n * 32 + 255) / 256, 256>>>(
        rs, deg, cedge, g1b, bA, bB, n);
    launch_fused<128, 128, 64, false, false>(bB, wf1, wf2, nullptr, bA, nullptr, n);

    // ---- layer 2 ----
    csr_agg_kernel<64, true, true><<<(n * 16 + 255) / 256, 256>>>(
        rs, deg, cedge, g3b, bA, bC, n);
    launch_std<64, 64, false, 1>(nullptr, bC, wf3, bA, n);

    // ---- layer 3 (aggregate first at d=64) ----
    csr_agg_kernel<64, false, false><<<(n * 16 + 255) / 256, 256>>>(
        rs, deg, cedge, nullptr, bA, bB, n);
    launch_fused<64, 128, 128, true, true>(bB, wf4, wf5, (float*)d_out, nullptr, g5b, n);
}

// round 17
// speedup vs baseline: 1.5961x; 1.0568x over previous
#include <cuda_runtime.h>
#include <cuda_bf16.h>
#include <math.h>
#include <stdint.h>

// ---------------------------------------------------------------------------
// GCN encoder on GB300: mma.sync bf16x3 GEMMs (64-row tiles, 2Mx4N warps) +
// CSR gather agg. Interleaved hi/lo bf16 intermediates; packed {src,norm}
// edge records; stream-forked prep (CSR build || wprep+GEMM1).
// ---------------------------------------------------------------------------

#define NMAX 100000
#define NPAD 100224
#define EMAX 2000000

__device__ int   g_deg[NMAX];
__device__ int   g_rs[NMAX];
__device__ int   g_cursor[NMAX];
__device__ int   g_blk[512];
__device__ int2  g_cedge[EMAX];     // {src, norm bits}
__device__ uint32_t g_bufA[(size_t)NPAD * 128];
__device__ uint32_t g_bufB[(size_t)NPAD * 128];
__device__ uint32_t g_bufC[(size_t)NPAD * 128];
__device__ uint32_t g_wfrag[6 * 16384];

// ------------------------------ small helpers ------------------------------

__device__ __forceinline__ uint32_t smem_u32(const void* p) {
    uint32_t a;
    asm("{ .reg .u64 t; cvta.to.shared.u64 t, %1; cvt.u32.u64 %0, t; }" : "=r"(a) : "l"(p));
    return a;
}

__device__ __forceinline__ float il2f(uint32_t w) {
    __nv_bfloat162 p = *(__nv_bfloat162*)&w;
    return __bfloat162float(p.x) + __bfloat162float(p.y);
}

__device__ __forceinline__ uint32_t f2il(float v) {
    __nv_bfloat162 p;
    p.x = __float2bfloat16(v);
    p.y = __float2bfloat16(v - __bfloat162float(p.x));
    return *(uint32_t*)&p;
}

__device__ __forceinline__ void mma_bf16(float* c, const uint32_t* a, uint32_t b0, uint32_t b1) {
    asm volatile(
        "mma.sync.aligned.m16n8k16.row.col.f32.bf16.bf16.f32 "
        "{%0,%1,%2,%3}, {%4,%5,%6,%7}, {%8,%9}, {%0,%1,%2,%3};"
        : "+f"(c[0]), "+f"(c[1]), "+f"(c[2]), "+f"(c[3])
        : "r"(a[0]), "r"(a[1]), "r"(a[2]), "r"(a[3]), "r"(b0), "r"(b1));
}

__device__ __forceinline__ void ldsm_x4(uint32_t* r, uint32_t addr) {
    asm volatile("ldmatrix.sync.aligned.m8n8.x4.shared.b16 {%0,%1,%2,%3}, [%4];"
                 : "=r"(r[0]), "=r"(r[1]), "=r"(r[2]), "=r"(r[3]) : "r"(addr));
}

// ------------------------------ CSR build ----------------------------------

__global__ void deg_zero_kernel(int* __restrict__ deg, int n) {
    int i = blockIdx.x * 256 + threadIdx.x;
    if (i < n) deg[i] = 0;
}

__global__ void deg_count_kernel(const int* __restrict__ dst, int* __restrict__ deg, int E) {
    int e = blockIdx.x * 256 + threadIdx.x;
    if (e < E) atomicAdd(&deg[dst[e]], 1);
}

__global__ void scan1_kernel(const int* __restrict__ deg, int* __restrict__ tmp,
                             int* __restrict__ blk, int n) {
    __shared__ int sh[256];
    int tid = threadIdx.x;
    int i = blockIdx.x * 256 + tid;
    int v = (i < n) ? deg[i] : 0;
    sh[tid] = v;
    __syncthreads();
#pragma unroll
    for (int off = 1; off < 256; off <<= 1) {
        int t = (tid >= off) ? sh[tid - off] : 0;
        __syncthreads();
        sh[tid] += t;
        __syncthreads();
    }
    if (i < n) tmp[i] = sh[tid];
    if (tid == 255) blk[blockIdx.x] = sh[255];
}

__global__ void scan2_kernel(int* __restrict__ blk, int nb) {
    __shared__ int sh[512];
    int tid = threadIdx.x;
    int v = (tid < nb) ? blk[tid] : 0;
    sh[tid] = v;
    __syncthreads();
#pragma unroll
    for (int off = 1; off < 512; off <<= 1) {
        int t = (tid >= off) ? sh[tid - off] : 0;
        __syncthreads();
        sh[tid] += t;
        __syncthreads();
    }
    if (tid < nb) blk[tid] = sh[tid] - v;   // exclusive
}

__global__ void scan3_kernel(const int* __restrict__ tmp, const int* __restrict__ deg,
                             const int* __restrict__ blk, int* __restrict__ rs,
                             int* __restrict__ cursor, int n) {
    int i = blockIdx.x * 256 + threadIdx.x;
    if (i < n) {
        int v = tmp[i] - deg[i] + blk[blockIdx.x];
        rs[i] = v;
        cursor[i] = v;
    }
}

__global__ void scatter_kernel(const int* __restrict__ src, const int* __restrict__ dst,
                               const int* __restrict__ deg, int* __restrict__ cursor,
                               int2* __restrict__ cedge, int E) {
    int e = blockIdx.x * 256 + threadIdx.x;
    if (e >= E) return;
    int s = __ldg(&src[e]);
    int d = __ldg(&dst[e]);
    int pos = atomicAdd(&cursor[d], 1);
    float nrm = rsqrtf((float)(__ldg(&deg[s]) + 1)) * rsqrtf((float)(__ldg(&deg[d]) + 1));
    cedge[pos] = make_int2(s, __float_as_int(nrm));
}

// ---------------------- CSR gather aggregation (interleaved IO) -------------

template <int D, bool BIAS, bool RELU>
__global__ void csr_agg_kernel(const int* __restrict__ rs, const int* __restrict__ deg,
                               const int2* __restrict__ cedge,
                               const float* __restrict__ bias,
                               const uint32_t* __restrict__ h, uint32_t* __restrict__ out,
                               int n) {
    constexpr int LN = D / 4;
    int t = blockIdx.x * 256 + threadIdx.x;
    int d = t / LN;
    int lane = t % LN;
    if (d >= n) return;
    int start = __ldg(&rs[d]);
    int dg = __ldg(&deg[d]);
    float inv = 1.0f / (float)(dg + 1);
    size_t coff = (size_t)lane * 4;
    uint4 w = __ldg((const uint4*)(h + (size_t)d * D + coff));
    float4 acc;
    acc.x = il2f(w.x) * inv; acc.y = il2f(w.y) * inv;
    acc.z = il2f(w.z) * inv; acc.w = il2f(w.w) * inv;
    if (BIAS) {
        float4 b = *(const float4*)(bias + coff);
        acc.x += b.x; acc.y += b.y; acc.z += b.z; acc.w += b.w;
    }
    int j = start, end = start + dg;
    for (; j + 2 <= end; j += 2) {
        int2 e0 = __ldg(&cedge[j]);
        int2 e1 = __ldg(&cedge[j + 1]);
        float n0 = __int_as_float(e0.y), n1 = __int_as_float(e1.y);
        uint4 w0 = __ldg((const uint4*)(h + (size_t)e0.x * D + coff));
        uint4 w1 = __ldg((const uint4*)(h + (size_t)e1.x * D + coff));
        acc.x += il2f(w0.x) * n0 + il2f(w1.x) * n1;
        acc.y += il2f(w0.y) * n0 + il2f(w1.y) * n1;
        acc.z += il2f(w0.z) * n0 + il2f(w1.z) * n1;
        acc.w += il2f(w0.w) * n0 + il2f(w1.w) * n1;
    }
    if (j < end) {
        int2 e0 = __ldg(&cedge[j]);
        float n0 = __int_as_float(e0.y);
        uint4 w0 = __ldg((const uint4*)(h + (size_t)e0.x * D + coff));
        acc.x += il2f(w0.x) * n0; acc.y += il2f(w0.y) * n0;
        acc.z += il2f(w0.z) * n0; acc.w += il2f(w0.w) * n0;
    }
    if (RELU) {
        acc.x = fmaxf(acc.x, 0.f); acc.y = fmaxf(acc.y, 0.f);
        acc.z = fmaxf(acc.z, 0.f); acc.w = fmaxf(acc.w, 0.f);
    }
    uint4 o;
    o.x = f2il(acc.x); o.y = f2il(acc.y); o.z = f2il(acc.z); o.w = f2il(acc.w);
    *(uint4*)(out + (size_t)d * D + coff) = o;
}

// ------------------------- weight fragment packing --------------------------

__global__ void wprep_all_kernel(const float* __restrict__ w0, const float* __restrict__ w1,
                                 const float* __restrict__ w2, const float* __restrict__ w3,
                                 const float* __restrict__ w4, const float* __restrict__ w5,
                                 uint32_t* __restrict__ wf) {
    int idx = blockIdx.x * 256 + threadIdx.x;
    int tile = idx >> 5;
    if (tile >= 544) return;
    int lane = idx & 31;

    const float* W;
    int K, N, slot, base;
    bool TR;
    if (tile < 128)      { slot = 0; base = 0;   W = w0; K = 128; N = 128; TR = true;  }
    else if (tile < 256) { slot = 1; base = 128; W = w1; K = 128; N = 128; TR = false; }
    else if (tile < 320) { slot = 2; base = 256; W = w2; K = 128; N = 64;  TR = true;  }
    else if (tile < 352) { slot = 3; base = 320; W = w3; K = 64;  N = 64;  TR = false; }
    else if (tile < 416) { slot = 4; base = 352; W = w4; K = 64;  N = 128; TR = true;  }
    else                 { slot = 5; base = 416; W = w5; K = 128; N = 128; TR = false; }

    int t = tile - base;
    int NT = N / 8;
    int nt = t % NT;
    int kt = t / NT;
    int g = lane >> 2, tig = lane & 3;
    int nn = nt * 8 + g;
    uint32_t* out = wf + slot * 16384;
    int LOFF = K * N / 2;

#pragma unroll
    for (int r = 0; r < 2; r++) {
        int k0 = kt * 16 + tig * 2 + r * 8;
        float v0 = TR ? W[(size_t)k0 * N + nn] : W[(size_t)nn * K + k0];
        float v1 = TR ? W[(size_t)(k0 + 1) * N + nn] : W[(size_t)nn * K + k0 + 1];
        __nv_bfloat16 h0 = __float2bfloat16(v0), h1 = __float2bfloat16(v1);
        float l0 = v0 - __bfloat162float(h0), l1 = v1 - __bfloat162float(h1);
        __nv_bfloat162 hp; hp.x = h0; hp.y = h1;
        __nv_bfloat162 lp; lp.x = __float2bfloat16(l0); lp.y = __float2bfloat16(l1);
        out[(size_t)(t * 32 + lane) * 2 + r] = *(uint32_t*)&hp;
        out[LOFF + (size_t)(t * 32 + lane) * 2 + r] = *(uint32_t*)&lp;
    }
}

// ----------------------------- GEMM mainloop --------------------------------
// 64-row tile: 8 warps = 2(M) x 4(N); each warp MT=2 m16 tiles, NW n8-tiles.

template <int LDA, int KT, int NT, int NW>
__device__ __forceinline__ void gemm_mainloop(uint32_t a_base, uint32_t l_base,
                                              const uint32_t* __restrict__ WF,
                                              int wn, int lane, float (*acc)[NW][4]) {
    constexpr int LOFF = KT * NT * 64;
#pragma unroll
    for (int kt = 0; kt < KT; kt++) {
        uint32_t ah[2][4], al[2][4];
#pragma unroll
        for (int mt = 0; mt < 2; mt++) {
            uint32_t off = (uint32_t)((mt * 16 * LDA + kt * 16) * 2);
            ldsm_x4(ah[mt], a_base + off);
            ldsm_x4(al[mt], l_base + off);
        }
#pragma unroll
        for (int nt = 0; nt < NW; nt++) {
            int gnt = wn * NW + nt;
            const uint32_t* bp = WF + ((size_t)(kt * NT + gnt) * 32 + lane) * 2;
            uint2 bh = *(const uint2*)bp;
            uint2 bl = *(const uint2*)(bp + LOFF);
#pragma unroll
            for (int mt = 0; mt < 2; mt++) {
                mma_bf16(acc[mt][nt], ah[mt], bh.x, bh.y);
                mma_bf16(acc[mt][nt], ah[mt], bl.x, bl.y);
                mma_bf16(acc[mt][nt], al[mt], bh.x, bh.y);
            }
        }
    }
}

// ----------------------------- standard GEMM --------------------------------
// EPI: 0 = raw, 1 = relu(A + d) (K==N). Output interleaved.

template <int K, int N, bool F32IN, int EPI>
__global__ void mma_gemm_kernel(
    const float* __restrict__ A32, const uint32_t* __restrict__ Ail,
    const uint32_t* __restrict__ WF, uint32_t* __restrict__ Cil, int n) {
    constexpr int LDA = K + 8;
    constexpr int NT = N / 8;
    constexpr int KT = K / 16;
    constexpr int NW = N / 32;      // n8-tiles per warp (WN=4)

    extern __shared__ __align__(16) char smem[];
    __nv_bfloat16* Ah = (__nv_bfloat16*)smem;
    __nv_bfloat16* Al = Ah + 64 * LDA;

    const int tid = threadIdx.x;
    const int w = tid >> 5;
    const int lane = tid & 31;
    const int g = lane >> 2, tig = lane & 3;
    const int row0 = blockIdx.x * 64;
    const int wm = w >> 2;          // 0..1 (32 rows each)
    const int wn = w & 3;           // 0..3
    const uint32_t smem_base = smem_u32(smem);

    if (F32IN) {
        constexpr int KQ = K / 4;
        for (int idx = tid; idx < 64 * KQ; idx += 256) {
            int r = idx / KQ;
            int k0 = (idx - r * KQ) * 4;
            float4 v = make_float4(0.f, 0.f, 0.f, 0.f);
            if (row0 + r < n) v = *(const float4*)(A32 + (size_t)(row0 + r) * K + k0);
            uint32_t i0 = f2il(v.x), i1 = f2il(v.y), i2 = f2il(v.z), i3 = f2il(v.w);
            *(uint2*)(Ah + r * LDA + k0) =
                make_uint2(__byte_perm(i0, i1, 0x5410), __byte_perm(i2, i3, 0x5410));
            *(uint2*)(Al + r * LDA + k0) =
                make_uint2(__byte_perm(i0, i1, 0x7632), __byte_perm(i2, i3, 0x7632));
        }
    } else {
        constexpr int KW = K / 4;
        for (int idx = tid; idx < 64 * KW; idx += 256) {
            int r = idx / KW;
            int c4 = idx - r * KW;
            uint4 v = __ldg((const uint4*)(Ail + (size_t)(row0 + r) * K + c4 * 4));
            *(uint2*)(Ah + r * LDA + c4 * 4) =
                make_uint2(__byte_perm(v.x, v.y, 0x5410), __byte_perm(v.z, v.w, 0x5410));
            *(uint2*)(Al + r * LDA + c4 * 4) =
                make_uint2(__byte_perm(v.x, v.y, 0x7632), __byte_perm(v.z, v.w, 0x7632));
        }
    }
    __syncthreads();

    float acc[2][NW][4];
#pragma unroll
    for (int mt = 0; mt < 2; mt++)
#pragma unroll
        for (int nt = 0; nt < NW; nt++)
#pragma unroll
            for (int i = 0; i < 4; i++) acc[mt][nt][i] = 0.f;

    const uint32_t a_base =
        smem_base + (uint32_t)(((wm * 32 + (lane & 15)) * LDA + (lane >> 4) * 8) * 2);
    const uint32_t l_base = a_base + (uint32_t)(64 * LDA * 2);
    gemm_mainloop<LDA, KT, NT, NW>(a_base, l_base, WF, wn, lane, acc);

#pragma unroll
    for (int mt = 0; mt < 2; mt++) {
#pragma unroll
        for (int h = 0; h < 2; h++) {
            int rloc = wm * 32 + mt * 16 + g + h * 8;
            int row = row0 + rloc;
            if (row >= n) continue;
#pragma unroll
            for (int nt = 0; nt < NW; nt++) {
                int col = (wn * NW + nt) * 8 + tig * 2;
                float v0 = acc[mt][nt][h * 2 + 0];
                float v1 = acc[mt][nt][h * 2 + 1];
                if (EPI == 1) {
                    __nv_bfloat162 rh = *(const __nv_bfloat162*)(Ah + rloc * LDA + col);
                    __nv_bfloat162 rl = *(const __nv_bfloat162*)(Al + rloc * LDA + col);
                    v0 = fmaxf(v0 + __bfloat162float(rh.x) + __bfloat162float(rl.x), 0.f);
                    v1 = fmaxf(v1 + __bfloat162float(rh.y) + __bfloat162float(rl.y), 0.f);
                }
                *(uint2*)(Cil + (size_t)row * N + col) = make_uint2(f2il(v0), f2il(v1));
            }
        }
    }
}

// ------------------------------ fused GEMM pair ------------------------------

template <int K1, int N1, int N2, bool BIAS1, bool OUTF32>
__global__ void fused_gemm_kernel(
    const uint32_t* __restrict__ Ail, const uint32_t* __restrict__ WF1,
    const uint32_t* __restrict__ WF2, float* __restrict__ C32,
    uint32_t* __restrict__ Cil, const float* __restrict__ bias1, int n) {
    constexpr int LDA1 = K1 + 8;
    constexpr int LDA2 = N1 + 8;
    constexpr bool INPLACE = !BIAS1;   // requires K1 == N1
    constexpr int KT1 = K1 / 16, NT1 = N1 / 8, NW1 = N1 / 32;
    constexpr int KT2 = N1 / 16, NT2 = N2 / 8, NW2 = N2 / 32;
    constexpr int MID_OFF = INPLACE ? 0 : 2 * 64 * LDA1;   // in bf16 elems

    extern __shared__ __align__(16) char smem[];
    __nv_bfloat16* Ah1 = (__nv_bfloat16*)smem;
    __nv_bfloat16* Al1 = Ah1 + 64 * LDA1;
    __nv_bfloat16* Ah2 = Ah1 + MID_OFF;
    __nv_bfloat16* Al2 = Ah2 + 64 * LDA2;

    const int tid = threadIdx.x;
    const int w = tid >> 5;
    const int lane = tid & 31;
    const int g = lane >> 2, tig = lane & 3;
    const int row0 = blockIdx.x * 64;
    const int wm = w >> 2;
    const int wn = w & 3;
    const uint32_t smem_base = smem_u32(smem);

    {
        constexpr int KW = K1 / 4;
        for (int idx = tid; idx < 64 * KW; idx += 256) {
            int r = idx / KW;
            int c4 = idx - r * KW;
            uint4 v = __ldg((const uint4*)(Ail + (size_t)(row0 + r) * K1 + c4 * 4));
            *(uint2*)(Ah1 + r * LDA1 + c4 * 4) =
                make_uint2(__byte_perm(v.x, v.y, 0x5410), __byte_perm(v.z, v.w, 0x5410));
            *(uint2*)(Al1 + r * LDA1 + c4 * 4) =
                make_uint2(__byte_perm(v.x, v.y, 0x7632), __byte_perm(v.z, v.w, 0x7632));
        }
    }
    __syncthreads();

    // ---- GEMM 1 ----
    {
        float acc[2][NW1][4];
#pragma unroll
        for (int mt = 0; mt < 2; mt++)
#pragma unroll
            for (int nt = 0; nt < NW1; nt++)
#pragma unroll
                for (int i = 0; i < 4; i++) acc[mt][nt][i] = 0.f;

        const uint32_t a_base =
            smem_base + (uint32_t)(((wm * 32 + (lane & 15)) * LDA1 + (lane >> 4) * 8) * 2);
        const uint32_t l_base = a_base + (uint32_t)(64 * LDA1 * 2);
        gemm_mainloop<LDA1, KT1, NT1, NW1>(a_base, l_base, WF1, wn, lane, acc);

        if (INPLACE) __syncthreads();

#pragma unroll
        for (int mt = 0; mt < 2; mt++) {
#pragma unroll
            for (int h = 0; h < 2; h++) {
                int rloc = wm * 32 + mt * 16 + g + h * 8;
#pragma unroll
                for (int nt = 0; nt < NW1; nt++) {
                    int col = (wn * NW1 + nt) * 8 + tig * 2;
                    float v0 = acc[mt][nt][h * 2 + 0];
                    float v1 = acc[mt][nt][h * 2 + 1];
                    if (BIAS1) {
                        v0 = fmaxf(v0 + __ldg(&bias1[col]), 0.f);
                        v1 = fmaxf(v1 + __ldg(&bias1[col + 1]), 0.f);
                    } else {
                        __nv_bfloat162 rh = *(const __nv_bfloat162*)(Ah1 + rloc * LDA1 + col);
                        __nv_bfloat162 rl = *(const __nv_bfloat162*)(Al1 + rloc * LDA1 + col);
                        v0 = fmaxf(v0 + __bfloat162float(rh.x) + __bfloat162float(rl.x), 0.f);
                        v1 = fmaxf(v1 + __bfloat162float(rh.y) + __bfloat162float(rl.y), 0.f);
                    }
                    __nv_bfloat16 h0 = __float2bfloat16(v0), h1 = __float2bfloat16(v1);
                    __nv_bfloat162 hp; hp.x = h0; hp.y = h1;
                    __nv_bfloat162 lp;
                    lp.x = __float2bfloat16(v0 - __bfloat162float(h0));
                    lp.y = __float2bfloat16(v1 - __bfloat162float(h1));
                    *(uint32_t*)(Ah2 + rloc * LDA2 + col) = *(uint32_t*)&hp;
                    *(uint32_t*)(Al2 + rloc * LDA2 + col) = *(uint32_t*)&lp;
                }
            }
        }
    }
    __syncthreads();

    // ---- GEMM 2 ----
    {
        float acc[2][NW2][4];
#pragma unroll
        for (int mt = 0; mt < 2; mt++)
#pragma unroll
            for (int nt = 0; nt < NW2; nt++)
#pragma unroll
                for (int i = 0; i < 4; i++) acc[mt][nt][i] = 0.f;

        const uint32_t a_base = smem_base + (uint32_t)(MID_OFF * 2) +
            (uint32_t)(((wm * 32 + (lane & 15)) * LDA2 + (lane >> 4) * 8) * 2);
        const uint32_t l_base = a_base + (uint32_t)(64 * LDA2 * 2);
        gemm_mainloop<LDA2, KT2, NT2, NW2>(a_base, l_base, WF2, wn, lane, acc);

#pragma unroll
        for (int mt = 0; mt < 2; mt++) {
#pragma unroll
            for (int h = 0; h < 2; h++) {
                int rloc = wm * 32 + mt * 16 + g + h * 8;
                int row = row0 + rloc;
                if (row >= n) continue;
#pragma unroll
                for (int nt = 0; nt < NW2; nt++) {
                    int col = (wn * NW2 + nt) * 8 + tig * 2;
                    float v0 = acc[mt][nt][h * 2 + 0];
                    float v1 = acc[mt][nt][h * 2 + 1];
                    if (OUTF32) {
                        __nv_bfloat162 rh = *(const __nv_bfloat162*)(Ah2 + rloc * LDA2 + col);
                        __nv_bfloat162 rl = *(const __nv_bfloat162*)(Al2 + rloc * LDA2 + col);
                        v0 = fmaxf(v0 + __bfloat162float(rh.x) + __bfloat162float(rl.x), 0.f);
                        v1 = fmaxf(v1 + __bfloat162float(rh.y) + __bfloat162float(rl.y), 0.f);
                        float2 o; o.x = v0; o.y = v1;
                        *(float2*)(C32 + (size_t)row * N2 + col) = o;
                    } else {
                        *(uint2*)(Cil + (size_t)row * N2 + col) = make_uint2(f2il(v0), f2il(v1));
                    }
                }
            }
        }
    }
}

// --------------------------------- launchers --------------------------------

template <int K, int N, bool F32IN, int EPI>
static void launch_std(const float* A32, const uint32_t* Ail, const uint32_t* WF,
                       uint32_t* Cil, int n) {
    constexpr int SMEM = 2 * 64 * (K + 8) * 2;
    auto kfn = mma_gemm_kernel<K, N, F32IN, EPI>;
    if (SMEM > 48 * 1024)
        cudaFuncSetAttribute(kfn, cudaFuncAttributeMaxDynamicSharedMemorySize, SMEM);
    kfn<<<(n + 63) / 64, 256, SMEM>>>(A32, Ail, WF, Cil, n);
}

template <int K1, int N1, int N2, bool BIAS1, bool OUTF32>
static void launch_fused(const uint32_t* Ail, const uint32_t* WF1, const uint32_t* WF2,
                         float* C32, uint32_t* Cil, const float* bias1, int n) {
    constexpr int SMEM = (BIAS1 ? (2 * 64 * (K1 + 8) + 2 * 64 * (N1 + 8))
                                : (2 * 64 * (K1 + 8))) * 2;
    auto kfn = fused_gemm_kernel<K1, N1, N2, BIAS1, OUTF32>;
    if (SMEM > 48 * 1024)
        cudaFuncSetAttribute(kfn, cudaFuncAttributeMaxDynamicSharedMemorySize, SMEM);
    kfn<<<(n + 63) / 64, 256, SMEM>>>(Ail, WF1, WF2, C32, Cil, bias1, n);
}

// --------------------------------- driver ----------------------------------

extern "C" void kernel_launch(void* const* d_in, const int* in_sizes, int n_in,
                              void* d_out, int out_size) {
    const float* x    = (const float*)d_in[0];
    const int*   ei   = (const int*)d_in[1];
    const float* g1w  = (const float*)d_in[2];
    const float* g1b  = (const float*)d_in[3];
    const float* fc2w = (const float*)d_in[4];
    const float* g3w  = (const float*)d_in[5];
    const float* g3b  = (const float*)d_in[6];
    const float* fc4w = (const float*)d_in[7];
    const float* g5w  = (const float*)d_in[8];
    const float* g5b  = (const float*)d_in[9];
    const float* fc6w = (const float*)d_in[10];

    int n = in_sizes[0] / 128;
    int E = in_sizes[1] / 2;
    const int* src = ei;
    const int* dst = ei + E;
    int nb = (n + 255) / 256;

    int *deg, *rs, *cursor, *blk;
    int2* cedge;
    uint32_t *bA, *bB, *bC, *wf;
    cudaGetSymbolAddress((void**)&deg, g_deg);
    cudaGetSymbolAddress((void**)&rs, g_rs);
    cudaGetSymbolAddress((void**)&cursor, g_cursor);
    cudaGetSymbolAddress((void**)&blk, g_blk);
    cudaGetSymbolAddress((void**)&cedge, g_cedge);
    cudaGetSymbolAddress((void**)&bA, g_bufA);
    cudaGetSymbolAddress((void**)&bB, g_bufB);
    cudaGetSymbolAddress((void**)&bC, g_bufC);
    cudaGetSymbolAddress((void**)&wf, g_wfrag);
    uint32_t* wf0 = wf;
    uint32_t* wf1 = wf + 16384;
    uint32_t* wf2 = wf + 2 * 16384;
    uint32_t* wf3 = wf + 3 * 16384;
    uint32_t* wf4 = wf + 4 * 16384;
    uint32_t* wf5 = wf + 5 * 16384;

    static cudaStream_t s_side = nullptr;
    static cudaEvent_t s_evF = nullptr, s_evJ = nullptr;
    if (!s_side) {
        cudaStreamCreateWithFlags(&s_side, cudaStreamNonBlocking);
        cudaEventCreateWithFlags(&s_evF, cudaEventDisableTiming);
        cudaEventCreateWithFlags(&s_evJ, cudaEventDisableTiming);
    }

    // ---- fork: CSR build on side stream, wprep+GEMM1 on main stream ----
    cudaEventRecord(s_evF, 0);
    cudaStreamWaitEvent(s_side, s_evF, 0);

    deg_zero_kernel<<<nb, 256, 0, s_side>>>(deg, n);
    deg_count_kernel<<<(E + 255) / 256, 256, 0, s_side>>>(dst, deg, E);
    scan1_kernel<<<nb, 256, 0, s_side>>>(deg, cursor, blk, n);
    scan2_kernel<<<1, 512, 0, s_side>>>(blk, nb);
    scan3_kernel<<<nb, 256, 0, s_side>>>(cursor, deg, blk, rs, cursor, n);
    scatter_kernel<<<(E + 255) / 256, 256, 0, s_side>>>(src, dst, deg, cursor, cedge, E);
    cudaEventRecord(s_evJ, s_side);

    wprep_all_kernel<<<68, 256>>>(g1w, fc2w, g3w, fc4w, g5w, fc6w, wf);
    launch_std<128, 128, true, 0>(x, nullptr, wf0, bA, n);   // bA = x @ W1

    // ---- join ----
    cudaStreamWaitEvent(0, s_evJ, 0);

    // ---- layer 1 ----
    csr_agg_kernel<128, true, true><<<(n * 32 + 255) / 256, 256>>>(
        rs, deg, cedge, g1b, bA, bB, n);
    launch_fused<128, 128, 64, false, false>(bB, wf1, wf2, nullptr, bA, nullptr, n);

    // ---- layer 2 ----
    csr_agg_kernel<64, true, true><<<(n * 16 + 255) / 256, 256>>>(
        rs, deg, cedge, g3b, bA, bC, n);
    launch_std<64, 64, false, 1>(nullptr, bC, wf3, bA, n);

    // ---- layer 3 (aggregate first at d=64) ----
    csr_agg_kernel<64, false, false><<<(n * 16 + 255) / 256, 256>>>(
        rs, deg, cedge, nullptr, bA, bB, n);
    launch_fused<64, 128, 128, true, true>(bB, wf4, wf5, (float*)d_out, nullptr, g5b, n);
}